// round 1
// baseline (speedup 1.0000x reference)
#include <cuda_runtime.h>
#include <math.h>

// ---- static problem config ----
namespace {
constexpr int Hc = 1024, HDc = 64, NQc = 16, NKVc = 4, Ec = 8, FFNc = 1024;
constexpr int Bc = 4, Qc = 128, Pc = 8, PSc = 128, Sc = 1024, Tc = 512;
constexpr int QKVW = HDc * (NQc + 2 * NKVc);   // 1536
constexpr float SCALEc = 0.125f;               // 64^-0.5
constexpr float ALPHAc = 1.702f, LIMITc = 7.0f, EPSc = 1e-5f;
}

// ---- scratch (static __device__, allocation-free) ----
__device__ float g_xnorm[Tc * Hc];
__device__ float g_qkv[Tc * QKVW];
__device__ float g_attn[Tc * Hc];
__device__ float g_h[Tc * Hc];
__device__ float g_x2[Tc * Hc];
__device__ float g_act[Tc * 2 * FFNc];   // per-slot activated intermediate
__device__ float g_eo[Tc * 2 * Hc];      // per-slot expert output
__device__ int   g_eidx[Tc * 2];
__device__ float g_ewt[Tc * 2];
__device__ int   g_cnt[Ec];
__device__ int   g_off[Ec];
__device__ int   g_tok[Tc * 2];
__device__ int   g_slotof[Tc * 2];

// ============================================================
// RMSNorm (ln1): y = x * w * rsqrt(mean(x^2)+eps)
// ============================================================
__global__ void rmsnorm1_kernel(const float* __restrict__ x,
                                const float* __restrict__ w,
                                float* __restrict__ y) {
    int t = blockIdx.x, tid = threadIdx.x;
    const float* xr = x + (size_t)t * Hc;
    float ss = 0.f;
#pragma unroll
    for (int i = 0; i < 4; i++) { float v = xr[tid + 256 * i]; ss += v * v; }
#pragma unroll
    for (int o = 16; o; o >>= 1) ss += __shfl_xor_sync(~0u, ss, o);
    __shared__ float red[8];
    if ((tid & 31) == 0) red[tid >> 5] = ss;
    __syncthreads();
    float tot = 0.f;
#pragma unroll
    for (int i = 0; i < 8; i++) tot += red[i];
    float rinv = rsqrtf(tot * (1.0f / Hc) + EPSc);
#pragma unroll
    for (int i = 0; i < 4; i++) {
        int c = tid + 256 * i;
        y[(size_t)t * Hc + c] = xr[c] * w[c] * rinv;
    }
}

// ============================================================
// Tiled SGEMM: C[M,N] = A[M,K] @ B[K,N] + bias[N] (+ resid[M,N])
// 64x64 tile, BK=16, 256 threads, 4x4 per thread
// ============================================================
__global__ __launch_bounds__(256) void sgemm_kernel(
    const float* __restrict__ A, const float* __restrict__ B,
    const float* __restrict__ bias, const float* __restrict__ resid,
    float* __restrict__ C, int M, int N, int K) {
    __shared__ float As[16][64];
    __shared__ float Bs[16][64];
    int row0 = blockIdx.y * 64, col0 = blockIdx.x * 64;
    int t = threadIdx.x;
    int a_m = t >> 2, a_k = (t & 3) << 2;
    int b_k = t >> 4, b_n = (t & 15) << 2;
    int tm = (t >> 4) << 2, tn = (t & 15) << 2;
    float acc[4][4] = {};
    const float* Ap = A + (size_t)(row0 + a_m) * K + a_k;
    const float* Bp = B + (size_t)b_k * N + col0 + b_n;
    for (int k0 = 0; k0 < K; k0 += 16) {
        float4 av = *(const float4*)(Ap + k0);
        As[a_k + 0][a_m] = av.x; As[a_k + 1][a_m] = av.y;
        As[a_k + 2][a_m] = av.z; As[a_k + 3][a_m] = av.w;
        *(float4*)(&Bs[b_k][b_n]) = *(const float4*)(Bp + (size_t)k0 * N);
        __syncthreads();
#pragma unroll
        for (int kk = 0; kk < 16; kk++) {
            float4 a = *(const float4*)(&As[kk][tm]);
            float4 b = *(const float4*)(&Bs[kk][tn]);
            float ar[4] = {a.x, a.y, a.z, a.w};
            float br[4] = {b.x, b.y, b.z, b.w};
#pragma unroll
            for (int i = 0; i < 4; i++)
#pragma unroll
                for (int j = 0; j < 4; j++) acc[i][j] += ar[i] * br[j];
        }
        __syncthreads();
    }
#pragma unroll
    for (int i = 0; i < 4; i++) {
        int r = row0 + tm + i;
#pragma unroll
        for (int j = 0; j < 4; j++) {
            int c = col0 + tn + j;
            float v = acc[i][j] + bias[c];
            if (resid) v += resid[(size_t)r * N + c];
            C[(size_t)r * N + c] = v;
        }
    }
}

// ============================================================
// Windowed GQA attention with sink.
// Window is exactly 128 keys: kpos in [qpos-127, qpos], qpos=896+q.
// One block per (head, q, batch); 128 threads (one per key).
// ============================================================
__global__ void attn_kernel(const float* __restrict__ qkvb,
                            const float* __restrict__ kvc,
                            const int* __restrict__ pidx,
                            const float* __restrict__ sinks,
                            float* __restrict__ attnout) {
    int h = blockIdx.x, q = blockIdx.y, b = blockIdx.z;
    int tid = threadIdx.x;  // 0..127
    int t = b * Qc + q;
    int qpos = (Sc - Qc) + q;          // 896+q
    int w0 = qpos - 127;
    int kvh = h >> 2;                  // G = 4

    __shared__ float qs[HDc];
    __shared__ float pr[128];
    __shared__ long long vbase[128];
    __shared__ float red_m[4], red_s[4];

    if (tid < HDc) qs[tid] = qkvb[(size_t)t * QKVW + h * HDc + tid] * SCALEc;

    int kpos = w0 + tid;
    const float* kptr;
    long long vb;
    if (kpos >= Sc - Qc) {  // new tokens from qkv buffer
        int tt = b * Qc + (kpos - (Sc - Qc));
        long long koff = (long long)tt * QKVW + (NQc + kvh) * HDc;
        long long voff = (long long)tt * QKVW + (NQc + NKVc + kvh) * HDc;
        kptr = qkvb + koff;
        vb = -voff - 1;  // negative => qkv-buffer source
    } else {                // paged cache
        int pg = pidx[b * Pc + (kpos >> 7)];
        long long base = (((long long)pg * 2 + 0) * PSc + (kpos & 127)) * (NKVc * HDc) + kvh * HDc;
        kptr = kvc + base;
        vb = base + (long long)PSc * NKVc * HDc;  // V plane = K plane + 32768
    }
    vbase[tid] = vb;
    __syncthreads();

    float s = 0.f;
#pragma unroll
    for (int d = 0; d < HDc; d++) s += qs[d] * kptr[d];

    // max reduce over 128 threads
    float m = s;
#pragma unroll
    for (int o = 16; o; o >>= 1) m = fmaxf(m, __shfl_xor_sync(~0u, m, o));
    if ((tid & 31) == 0) red_m[tid >> 5] = m;
    __syncthreads();
    m = fmaxf(fmaxf(red_m[0], red_m[1]), fmaxf(red_m[2], red_m[3]));

    float p = expf(s - m);
    pr[tid] = p;
    float sm = p;
#pragma unroll
    for (int o = 16; o; o >>= 1) sm += __shfl_xor_sync(~0u, sm, o);
    if ((tid & 31) == 0) red_s[tid >> 5] = sm;
    __syncthreads();
    float denom = red_s[0] + red_s[1] + red_s[2] + red_s[3] + expf(sinks[h] - m);

    if (tid < HDc) {
        float acc = 0.f;
#pragma unroll 4
        for (int s2 = 0; s2 < 128; s2++) {
            long long vb2 = vbase[s2];
            const float* vp = (vb2 < 0) ? (qkvb + (-vb2 - 1)) : (kvc + vb2);
            acc += pr[s2] * vp[tid];
        }
        attnout[(size_t)t * Hc + h * HDc + tid] = acc / denom;
    }
}

// ============================================================
// Router: rmsnorm(ln2) -> x2, logits, top-2 + softmax weights
// ============================================================
__global__ void router_kernel(const float* __restrict__ ln2,
                              const float* __restrict__ Wr,
                              const float* __restrict__ br) {
    int t = blockIdx.x, tid = threadIdx.x;
    __shared__ float sx[Hc];
    __shared__ float red[8];
    __shared__ float lg[Ec];
    const float* hr = g_h + (size_t)t * Hc;
    float ss = 0.f;
#pragma unroll
    for (int i = 0; i < 4; i++) { float v = hr[tid + 256 * i]; ss += v * v; }
#pragma unroll
    for (int o = 16; o; o >>= 1) ss += __shfl_xor_sync(~0u, ss, o);
    if ((tid & 31) == 0) red[tid >> 5] = ss;
    __syncthreads();
    float tot = 0.f;
#pragma unroll
    for (int i = 0; i < 8; i++) tot += red[i];
    float rinv = rsqrtf(tot * (1.0f / Hc) + EPSc);
#pragma unroll
    for (int i = 0; i < 4; i++) {
        int c = tid + 256 * i;
        float v = hr[c] * ln2[c] * rinv;
        sx[c] = v;
        g_x2[(size_t)t * Hc + c] = v;
    }
    __syncthreads();
    int w = tid >> 5, lane = tid & 31;
    float s = 0.f;
    for (int c = lane; c < Hc; c += 32) s += sx[c] * Wr[c * Ec + w];
#pragma unroll
    for (int o = 16; o; o >>= 1) s += __shfl_xor_sync(~0u, s, o);
    if (lane == 0) lg[w] = s + br[w];
    __syncthreads();
    if (tid == 0) {
        int i0 = 0; float v0 = lg[0];
#pragma unroll
        for (int e = 1; e < Ec; e++) if (lg[e] > v0) { v0 = lg[e]; i0 = e; }
        int i1 = -1; float v1 = -1e30f;
#pragma unroll
        for (int e = 0; e < Ec; e++) {
            if (e == i0) continue;
            if (lg[e] > v1) { v1 = lg[e]; i1 = e; }
        }
        float e1 = expf(v1 - v0);
        g_eidx[t * 2] = i0; g_eidx[t * 2 + 1] = i1;
        g_ewt[t * 2] = 1.0f / (1.0f + e1);
        g_ewt[t * 2 + 1] = e1 / (1.0f + e1);
    }
}

// ============================================================
// Bucket tokens by expert (single block)
// ============================================================
__global__ void bucket_kernel() {
    __shared__ int c1[Ec], c2[Ec], so[Ec];
    int tid = threadIdx.x;
    if (tid < Ec) { c1[tid] = 0; c2[tid] = 0; }
    __syncthreads();
    for (int i = tid; i < Tc * 2; i += blockDim.x) atomicAdd(&c1[g_eidx[i]], 1);
    __syncthreads();
    if (tid == 0) {
        int run = 0;
        for (int e = 0; e < Ec; e++) { so[e] = run; run += c1[e]; }
    }
    __syncthreads();
    if (tid < Ec) { g_cnt[tid] = c1[tid]; g_off[tid] = so[tid]; }
    for (int i = tid; i < Tc * 2; i += blockDim.x) {
        int e = g_eidx[i];
        int r = atomicAdd(&c2[e], 1);
        int slot = so[e] + r;
        g_tok[slot] = i >> 1;
        g_slotof[i] = slot;
    }
}

// ============================================================
// Expert gate_up GEMM (gathered rows) + swiglu epilogue -> g_act
// ============================================================
__global__ __launch_bounds__(256) void gemm_gateup_kernel(
    const float* __restrict__ Wgu, const float* __restrict__ Bgu) {
    int e = blockIdx.z;
    int cnt = g_cnt[e];
    int row0 = blockIdx.y * 64;
    if (row0 >= cnt) return;
    int off = g_off[e];
    int col0 = blockIdx.x * 64;
    __shared__ float As[16][64];
    __shared__ float Bs[16][64];
    int t = threadIdx.x;
    int a_m = t >> 2, a_k = (t & 3) << 2;
    int b_k = t >> 4, b_n = (t & 15) << 2;
    int tm = (t >> 4) << 2, tn = (t & 15) << 2;
    int tok = (row0 + a_m < cnt) ? g_tok[off + row0 + a_m] : -1;
    const float* Ap = (tok >= 0) ? (g_x2 + (size_t)tok * Hc + a_k) : nullptr;
    const int Nw = 2 * FFNc;
    const float* Bp = Wgu + (size_t)e * Hc * Nw + (size_t)b_k * Nw + col0 + b_n;
    float acc[4][4] = {};
    for (int k0 = 0; k0 < Hc; k0 += 16) {
        float4 av = Ap ? *(const float4*)(Ap + k0) : make_float4(0, 0, 0, 0);
        As[a_k + 0][a_m] = av.x; As[a_k + 1][a_m] = av.y;
        As[a_k + 2][a_m] = av.z; As[a_k + 3][a_m] = av.w;
        *(float4*)(&Bs[b_k][b_n]) = *(const float4*)(Bp + (size_t)k0 * Nw);
        __syncthreads();
#pragma unroll
        for (int kk = 0; kk < 16; kk++) {
            float4 a = *(const float4*)(&As[kk][tm]);
            float4 b = *(const float4*)(&Bs[kk][tn]);
            float ar[4] = {a.x, a.y, a.z, a.w};
            float br[4] = {b.x, b.y, b.z, b.w};
#pragma unroll
            for (int i = 0; i < 4; i++)
#pragma unroll
                for (int j = 0; j < 4; j++) acc[i][j] += ar[i] * br[j];
        }
        __syncthreads();
    }
    const float* bb = Bgu + (size_t)e * Nw + col0 + tn;
#pragma unroll
    for (int i = 0; i < 4; i++) {
        int r = row0 + tm + i;
        if (r >= cnt) break;
        int slot = off + r;
#pragma unroll
        for (int pp = 0; pp < 2; pp++) {
            float gv = acc[i][2 * pp + 0] + bb[2 * pp + 0];
            float uv = acc[i][2 * pp + 1] + bb[2 * pp + 1];
            gv = fminf(gv, LIMITc);
            uv = fminf(fmaxf(uv, -LIMITc), LIMITc);
            float glu = gv / (1.0f + expf(-ALPHAc * gv));
            g_act[(size_t)slot * FFNc + ((col0 + tn) >> 1) + pp] = (uv + 1.0f) * glu;
        }
    }
}

// ============================================================
// Expert down GEMM: g_eo[slot] = g_act[slot] @ w_down[e] + b_down[e]
// ============================================================
__global__ __launch_bounds__(256) void gemm_down_kernel(
    const float* __restrict__ Wd, const float* __restrict__ Bd) {
    int e = blockIdx.z;
    int cnt = g_cnt[e];
    int row0 = blockIdx.y * 64;
    if (row0 >= cnt) return;
    int off = g_off[e];
    int col0 = blockIdx.x * 64;
    __shared__ float As[16][64];
    __shared__ float Bs[16][64];
    int t = threadIdx.x;
    int a_m = t >> 2, a_k = (t & 3) << 2;
    int b_k = t >> 4, b_n = (t & 15) << 2;
    int tm = (t >> 4) << 2, tn = (t & 15) << 2;
    bool avalid = (row0 + a_m < cnt);
    const float* Ap = g_act + (size_t)(off + row0 + a_m) * FFNc + a_k;
    const float* Bp = Wd + (size_t)e * FFNc * Hc + (size_t)b_k * Hc + col0 + b_n;
    float acc[4][4] = {};
    for (int k0 = 0; k0 < FFNc; k0 += 16) {
        float4 av = avalid ? *(const float4*)(Ap + k0) : make_float4(0, 0, 0, 0);
        As[a_k + 0][a_m] = av.x; As[a_k + 1][a_m] = av.y;
        As[a_k + 2][a_m] = av.z; As[a_k + 3][a_m] = av.w;
        *(float4*)(&Bs[b_k][b_n]) = *(const float4*)(Bp + (size_t)k0 * Hc);
        __syncthreads();
#pragma unroll
        for (int kk = 0; kk < 16; kk++) {
            float4 a = *(const float4*)(&As[kk][tm]);
            float4 b = *(const float4*)(&Bs[kk][tn]);
            float ar[4] = {a.x, a.y, a.z, a.w};
            float br[4] = {b.x, b.y, b.z, b.w};
#pragma unroll
            for (int i = 0; i < 4; i++)
#pragma unroll
                for (int j = 0; j < 4; j++) acc[i][j] += ar[i] * br[j];
        }
        __syncthreads();
    }
    const float* bb = Bd + (size_t)e * Hc + col0 + tn;
#pragma unroll
    for (int i = 0; i < 4; i++) {
        int r = row0 + tm + i;
        if (r >= cnt) break;
        int slot = off + r;
#pragma unroll
        for (int j = 0; j < 4; j++)
            g_eo[(size_t)slot * Hc + col0 + tn + j] = acc[i][j] + bb[j];
    }
}

// ============================================================
// Final combine: out = h + w0*eo[slot0] + w1*eo[slot1]
// ============================================================
__global__ void combine_kernel(float* __restrict__ out) {
    int t = blockIdx.x, tid = threadIdx.x;
    float w0 = g_ewt[t * 2], w1 = g_ewt[t * 2 + 1];
    int s0 = g_slotof[t * 2], s1 = g_slotof[t * 2 + 1];
#pragma unroll
    for (int i = 0; i < 4; i++) {
        int c = tid + 256 * i;
        out[(size_t)t * Hc + c] = g_h[(size_t)t * Hc + c]
                                + w0 * g_eo[(size_t)s0 * Hc + c]
                                + w1 * g_eo[(size_t)s1 * Hc + c];
    }
}

// ============================================================
extern "C" void kernel_launch(void* const* d_in, const int* in_sizes, int n_in,
                              void* d_out, int out_size) {
    const float* hidden = (const float*)d_in[0];
    const float* kvc    = (const float*)d_in[1];
    // d_in[2] attention_mask: exactly causal; subsumed by window loop
    const int*   pidx   = (const int*)d_in[3];
    const float* sinks  = (const float*)d_in[4];
    const float* w_qkv  = (const float*)d_in[5];
    const float* b_qkv  = (const float*)d_in[6];
    const float* w_o    = (const float*)d_in[7];
    const float* b_o    = (const float*)d_in[8];
    const float* ln1    = (const float*)d_in[9];
    const float* ln2    = (const float*)d_in[10];
    const float* w_r    = (const float*)d_in[11];
    const float* b_r    = (const float*)d_in[12];
    const float* w_gu   = (const float*)d_in[13];
    const float* b_gu   = (const float*)d_in[14];
    const float* w_d    = (const float*)d_in[15];
    const float* b_d    = (const float*)d_in[16];
    float* out = (float*)d_out;

    void *px, *pq, *pa, *ph;
    cudaGetSymbolAddress(&px, g_xnorm);
    cudaGetSymbolAddress(&pq, g_qkv);
    cudaGetSymbolAddress(&pa, g_attn);
    cudaGetSymbolAddress(&ph, g_h);

    // 1) ln1
    rmsnorm1_kernel<<<Tc, 256>>>(hidden, ln1, (float*)px);
    // 2) QKV GEMM: [512,1536] = xnorm @ w_qkv + b
    {
        dim3 g(QKVW / 64, Tc / 64);
        sgemm_kernel<<<g, 256>>>((const float*)px, w_qkv, b_qkv, nullptr,
                                 (float*)pq, Tc, QKVW, Hc);
    }
    // 3) attention
    {
        dim3 g(NQc, Qc, Bc);
        attn_kernel<<<g, 128>>>((const float*)pq, kvc, pidx, sinks, (float*)pa);
    }
    // 4) O proj + residual: h = hidden + attn @ w_o + b_o
    {
        dim3 g(Hc / 64, Tc / 64);
        sgemm_kernel<<<g, 256>>>((const float*)pa, w_o, b_o, hidden,
                                 (float*)ph, Tc, Hc, Hc);
    }
    // 5) router (ln2 + logits + top2)
    router_kernel<<<Tc, 256>>>(ln2, w_r, b_r);
    // 6) bucket tokens by expert
    bucket_kernel<<<1, 256>>>();
    // 7) gate_up GEMM + swiglu (sparse, gathered)
    {
        dim3 g(2 * FFNc / 64, Tc / 64, Ec);
        gemm_gateup_kernel<<<g, 256>>>(w_gu, b_gu);
    }
    // 8) down GEMM
    {
        dim3 g(Hc / 64, Tc / 64, Ec);
        gemm_down_kernel<<<g, 256>>>(w_d, b_d);
    }
    // 9) combine into output
    combine_kernel<<<Tc, 256>>>(out);
}

// round 3
// speedup vs baseline: 1.5751x; 1.5751x over previous
#include <cuda_runtime.h>
#include <cuda_bf16.h>
#include <math.h>
#include <stdint.h>

// ---- static problem config ----
namespace {
constexpr int Hc = 1024, HDc = 64, NQc = 16, NKVc = 4, Ec = 8, FFNc = 1024;
constexpr int Bc = 4, Qc = 128, Pc = 8, PSc = 128, Sc = 1024, Tc = 512;
constexpr int QKVW = HDc * (NQc + 2 * NKVc);   // 1536
constexpr float SCALEc = 0.125f;
constexpr float ALPHAc = 1.702f, LIMITc = 7.0f, EPSc = 1e-5f;
// smem: double buffer x (AH 8K | AL 8K | BH 16K | BL 16K) = 96KB
constexpr uint32_t ASZ = 64 * 64 * 2;          // 8192
constexpr uint32_t BSZ = 128 * 64 * 2;         // 16384
constexpr uint32_t BUFSZ = 2 * ASZ + 2 * BSZ;  // 49152
constexpr int GEMM_SMEM = 2 * (int)BUFSZ + 1024;
}

// ---- scratch (static __device__, allocation-free) ----
__device__ float g_xnorm[Tc * Hc];
__device__ float g_qkv[Tc * QKVW];
__device__ float g_attn[Tc * Hc];
__device__ float g_h[Tc * Hc];
__device__ float g_x2[Tc * Hc];
__device__ __nv_bfloat16 g_act_hi[Tc * 2 * FFNc];
__device__ __nv_bfloat16 g_act_lo[Tc * 2 * FFNc];
__device__ float g_eo[Tc * 2 * Hc];
__device__ int   g_eidx[Tc * 2];
__device__ float g_ewt[Tc * 2];
__device__ int   g_cnt[Ec];
__device__ int   g_off[Ec];
__device__ int   g_tok[Tc * 2];
__device__ int   g_slotof[Tc * 2];

// ============================================================
__device__ __forceinline__ uint32_t smem_to_u32(const void* p) {
    uint32_t a;
    asm("{ .reg .u64 t; cvta.to.shared.u64 t, %1; cvt.u32.u64 %0, t; }" : "=r"(a) : "l"(p));
    return a;
}
__device__ __forceinline__ void st_s32(uint32_t a, uint32_t v) {
    asm volatile("st.shared.b32 [%0], %1;" :: "r"(a), "r"(v));
}
__device__ __forceinline__ void ldm_x4(uint32_t& r0, uint32_t& r1, uint32_t& r2,
                                       uint32_t& r3, uint32_t addr) {
    asm volatile("ldmatrix.sync.aligned.m8n8.x4.shared.b16 {%0,%1,%2,%3}, [%4];"
                 : "=r"(r0), "=r"(r1), "=r"(r2), "=r"(r3) : "r"(addr));
}
__device__ __forceinline__ void mma_bf16(float* c, const uint32_t* a, const uint32_t* b) {
    asm volatile(
        "mma.sync.aligned.m16n8k16.row.col.f32.bf16.bf16.f32 "
        "{%0,%1,%2,%3}, {%4,%5,%6,%7}, {%8,%9}, {%0,%1,%2,%3};"
        : "+f"(c[0]), "+f"(c[1]), "+f"(c[2]), "+f"(c[3])
        : "r"(a[0]), "r"(a[1]), "r"(a[2]), "r"(a[3]), "r"(b[0]), "r"(b[1]));
}
// split two floats into packed bf16 hi/lo and store swizzled (SW128 on 128B rows)
__device__ __forceinline__ void store_pair(uint32_t AH, uint32_t AL, uint32_t byte_off,
                                           float x, float y) {
    __nv_bfloat16 hx = __float2bfloat16(x), hy = __float2bfloat16(y);
    __nv_bfloat16 lx = __float2bfloat16(x - __bfloat162float(hx));
    __nv_bfloat16 ly = __float2bfloat16(y - __bfloat162float(hy));
    uint32_t hp = ((uint32_t)__bfloat16_as_ushort(hy) << 16) | __bfloat16_as_ushort(hx);
    uint32_t lp = ((uint32_t)__bfloat16_as_ushort(ly) << 16) | __bfloat16_as_ushort(lx);
    uint32_t sw = byte_off ^ ((byte_off >> 3) & 0x70);
    st_s32(AH + sw, hp);
    st_s32(AL + sw, lp);
}

// ============================================================
// HMMA GEMM: C[64,128] tile, K=1024 in 16 blocks of 64, split-bf16 (3 MMA)
// MODE: 0=QKV, 1=OPROJ(+resid), 2=GATEUP(gather+swiglu->act), 3=DOWN(act->eo)
// ============================================================
template <int MODE, int NN>
__global__ __launch_bounds__(256, 1) void mma_gemm(
    const float* __restrict__ A, const float* __restrict__ Bw,
    const float* __restrict__ bias, const float* __restrict__ resid,
    float* __restrict__ Cout) {
    extern __shared__ __align__(1024) char dsm[];
    __shared__ int s_tok[64];

    const int tid = threadIdx.x, wid = tid >> 5, lane = tid & 31;
    const int wm = wid & 1, wn = wid >> 1;
    const int e = blockIdx.z;
    const int row0 = blockIdx.y * 64, col0 = blockIdx.x * 128;
    int cnt = Tc, off = 0;
    if (MODE >= 2) {
        cnt = g_cnt[e];
        off = g_off[e];
        if (row0 >= cnt) return;
    }
    const float* Bg = Bw + (MODE >= 2 ? (size_t)e * 1024 * NN : 0);

    uint32_t base = (smem_to_u32(dsm) + 1023) & ~1023u;

    if (MODE == 2 && tid < 64) {
        int r = row0 + tid;
        s_tok[tid] = (r < cnt) ? g_tok[off + r] : -1;
    }
    if (MODE == 2) __syncthreads();

    // per-thread staging info
    const int b_n = tid & 127, b_kh = (tid >> 7) * 32;
    float aF[16];
    uint32_t aU[16];
    float bF[32];

    // ---- register load of K-block kb ----
    auto ld_regs = [&](int kb) {
        const int kbase = kb * 64;
        if (MODE == 3) {
#pragma unroll
            for (int i = 0; i < 4; i++) {
                int idx = tid + 256 * i;
                int rr = idx >> 4, fc = (idx & 15) << 2;
                uint2 hv = make_uint2(0u, 0u), lv = make_uint2(0u, 0u);
                if (row0 + rr < cnt) {
                    size_t p = (size_t)(off + row0 + rr) * FFNc + kbase + fc;
                    hv = *(const uint2*)(g_act_hi + p);
                    lv = *(const uint2*)(g_act_lo + p);
                }
                aU[4 * i + 0] = hv.x; aU[4 * i + 1] = hv.y;
                aU[4 * i + 2] = lv.x; aU[4 * i + 3] = lv.y;
            }
        } else {
#pragma unroll
            for (int i = 0; i < 4; i++) {
                int idx = tid + 256 * i;
                int rr = idx >> 4, fc = (idx & 15) << 2;
                float4 v = make_float4(0.f, 0.f, 0.f, 0.f);
                if (MODE == 2) {
                    int tok = s_tok[rr];
                    if (tok >= 0) v = *(const float4*)(g_x2 + (size_t)tok * Hc + kbase + fc);
                } else {
                    v = *(const float4*)(A + (size_t)(row0 + rr) * Hc + kbase + fc);
                }
                aF[4 * i + 0] = v.x; aF[4 * i + 1] = v.y;
                aF[4 * i + 2] = v.z; aF[4 * i + 3] = v.w;
            }
        }
        const float* bp = Bg + (size_t)(kbase + b_kh) * NN + col0 + b_n;
#pragma unroll
        for (int kk = 0; kk < 32; kk++) bF[kk] = bp[(size_t)kk * NN];
    };
    // ---- store staged regs into smem buffer (with bf16 hi/lo split) ----
    auto st_regs = [&](uint32_t buf) {
        uint32_t AH = buf, AL = buf + ASZ, BH = buf + 2 * ASZ, BL = BH + BSZ;
#pragma unroll
        for (int i = 0; i < 4; i++) {
            int idx = tid + 256 * i;
            int rr = idx >> 4, fc = (idx & 15) << 2;
            uint32_t b0 = rr * 128 + fc * 2;
            if (MODE == 3) {
                uint32_t s0 = b0 ^ ((b0 >> 3) & 0x70);
                uint32_t b1 = b0 + 4;
                uint32_t s1 = b1 ^ ((b1 >> 3) & 0x70);
                st_s32(AH + s0, aU[4 * i + 0]); st_s32(AH + s1, aU[4 * i + 1]);
                st_s32(AL + s0, aU[4 * i + 2]); st_s32(AL + s1, aU[4 * i + 3]);
            } else {
                store_pair(AH, AL, b0, aF[4 * i + 0], aF[4 * i + 1]);
                store_pair(AH, AL, b0 + 4, aF[4 * i + 2], aF[4 * i + 3]);
            }
        }
#pragma unroll
        for (int kk = 0; kk < 32; kk += 2)
            store_pair(BH, BL, b_n * 128 + (b_kh + kk) * 2, bF[kk], bF[kk + 1]);
    };

    float acc[2][4][4] = {};

    // ldmatrix lane address bases (byte offsets within tile, pre-swizzle)
    const uint32_t a_raw0 = (uint32_t)(wm * 32 + (lane & 15)) * 128 + (lane >> 4) * 16;
    const int b_grp = lane >> 3;
    const uint32_t b_raw0 =
        (uint32_t)(wn * 32 + ((b_grp >> 1) << 3) + (lane & 7)) * 128 + (b_grp & 1) * 16;

    auto compute = [&](uint32_t buf) {
        uint32_t AH = buf, AL = buf + ASZ, BH = buf + 2 * ASZ, BL = BH + BSZ;
#pragma unroll
        for (int ks = 0; ks < 4; ks++) {
            uint32_t ah[2][4], al[2][4], bh[4][2], bl[4][2];
#pragma unroll
            for (int mi = 0; mi < 2; mi++) {
                uint32_t raw = a_raw0 + mi * 2048 + ks * 32;
                uint32_t sw = raw ^ ((raw >> 3) & 0x70);
                ldm_x4(ah[mi][0], ah[mi][1], ah[mi][2], ah[mi][3], AH + sw);
                ldm_x4(al[mi][0], al[mi][1], al[mi][2], al[mi][3], AL + sw);
            }
#pragma unroll
            for (int np = 0; np < 2; np++) {
                uint32_t raw = b_raw0 + np * 2048 + ks * 32;
                uint32_t sw = raw ^ ((raw >> 3) & 0x70);
                ldm_x4(bh[2 * np][0], bh[2 * np][1], bh[2 * np + 1][0], bh[2 * np + 1][1],
                       BH + sw);
                ldm_x4(bl[2 * np][0], bl[2 * np][1], bl[2 * np + 1][0], bl[2 * np + 1][1],
                       BL + sw);
            }
#pragma unroll
            for (int mi = 0; mi < 2; mi++)
#pragma unroll
                for (int ni = 0; ni < 4; ni++) {
                    mma_bf16(acc[mi][ni], ah[mi], bh[ni]);
                    mma_bf16(acc[mi][ni], ah[mi], bl[ni]);
                    mma_bf16(acc[mi][ni], al[mi], bh[ni]);
                }
        }
    };

    ld_regs(0);
    st_regs(base);
    __syncthreads();
    for (int kb = 0; kb < 16; kb++) {
        if (kb + 1 < 16) ld_regs(kb + 1);          // LDGs in flight during MMA
        compute(base + (kb & 1) * BUFSZ);
        if (kb + 1 < 16) st_regs(base + ((kb + 1) & 1) * BUFSZ);
        __syncthreads();
    }

    // ---- epilogue from registers ----
    const int g = lane >> 2, tg = lane & 3;
#pragma unroll
    for (int mi = 0; mi < 2; mi++) {
#pragma unroll
        for (int ni = 0; ni < 4; ni++) {
#pragma unroll
            for (int hh = 0; hh < 2; hh++) {   // hh: +0 / +8 row halves
                int r = row0 + wm * 32 + mi * 16 + g + hh * 8;
                int c = col0 + wn * 32 + ni * 8 + tg * 2;
                float v0 = acc[mi][ni][2 * hh + 0];
                float v1 = acc[mi][ni][2 * hh + 1];
                if (MODE == 0) {
                    size_t p = (size_t)r * NN + c;
                    Cout[p] = v0 + bias[c];
                    Cout[p + 1] = v1 + bias[c + 1];
                } else if (MODE == 1) {
                    size_t p = (size_t)r * NN + c;
                    Cout[p] = v0 + bias[c] + resid[p];
                    Cout[p + 1] = v1 + bias[c + 1] + resid[p + 1];
                } else if (MODE == 2) {
                    if (r < cnt) {
                        const float* bg = bias + (size_t)e * 2 * FFNc;
                        float gv = v0 + bg[c];
                        float uv = v1 + bg[c + 1];
                        gv = fminf(gv, LIMITc);
                        uv = fminf(fmaxf(uv, -LIMITc), LIMITc);
                        float glu = gv / (1.0f + expf(-ALPHAc * gv));
                        float a = (uv + 1.0f) * glu;
                        __nv_bfloat16 h = __float2bfloat16(a);
                        __nv_bfloat16 l = __float2bfloat16(a - __bfloat162float(h));
                        size_t p = (size_t)(off + r) * FFNc + (c >> 1);
                        g_act_hi[p] = h;
                        g_act_lo[p] = l;
                    }
                } else {
                    if (r < cnt) {
                        const float* bd = bias + (size_t)e * Hc;
                        size_t p = (size_t)(off + r) * Hc + c;
                        g_eo[p] = v0 + bd[c];
                        g_eo[p + 1] = v1 + bd[c + 1];
                    }
                }
            }
        }
    }
}

// ============================================================
// RMSNorm (ln1)
// ============================================================
__global__ void rmsnorm1_kernel(const float* __restrict__ x,
                                const float* __restrict__ w,
                                float* __restrict__ y) {
    int t = blockIdx.x, tid = threadIdx.x;
    const float* xr = x + (size_t)t * Hc;
    float ss = 0.f;
#pragma unroll
    for (int i = 0; i < 4; i++) { float v = xr[tid + 256 * i]; ss += v * v; }
#pragma unroll
    for (int o = 16; o; o >>= 1) ss += __shfl_xor_sync(~0u, ss, o);
    __shared__ float red[8];
    if ((tid & 31) == 0) red[tid >> 5] = ss;
    __syncthreads();
    float tot = 0.f;
#pragma unroll
    for (int i = 0; i < 8; i++) tot += red[i];
    float rinv = rsqrtf(tot * (1.0f / Hc) + EPSc);
#pragma unroll
    for (int i = 0; i < 4; i++) {
        int c = tid + 256 * i;
        y[(size_t)t * Hc + c] = xr[c] * w[c] * rinv;
    }
}

// ============================================================
// Windowed GQA attention with sink (window = exactly 128 keys)
// ============================================================
__global__ void attn_kernel(const float* __restrict__ qkvb,
                            const float* __restrict__ kvc,
                            const int* __restrict__ pidx,
                            const float* __restrict__ sinks,
                            float* __restrict__ attnout) {
    int h = blockIdx.x, q = blockIdx.y, b = blockIdx.z;
    int tid = threadIdx.x;
    int t = b * Qc + q;
    int qpos = (Sc - Qc) + q;
    int w0 = qpos - 127;
    int kvh = h >> 2;

    __shared__ float qs[HDc];
    __shared__ float pr[128];
    __shared__ long long vbase[128];
    __shared__ float red_m[4], red_s[4];

    if (tid < HDc) qs[tid] = qkvb[(size_t)t * QKVW + h * HDc + tid] * SCALEc;

    int kpos = w0 + tid;
    const float* kptr;
    long long vb;
    if (kpos >= Sc - Qc) {
        int tt = b * Qc + (kpos - (Sc - Qc));
        long long koff = (long long)tt * QKVW + (NQc + kvh) * HDc;
        long long voff = (long long)tt * QKVW + (NQc + NKVc + kvh) * HDc;
        kptr = qkvb + koff;
        vb = -voff - 1;
    } else {
        int pg = pidx[b * Pc + (kpos >> 7)];
        long long base = (((long long)pg * 2 + 0) * PSc + (kpos & 127)) * (NKVc * HDc) + kvh * HDc;
        kptr = kvc + base;
        vb = base + (long long)PSc * NKVc * HDc;
    }
    vbase[tid] = vb;
    __syncthreads();

    float s = 0.f;
#pragma unroll
    for (int d = 0; d < HDc; d++) s += qs[d] * kptr[d];

    float m = s;
#pragma unroll
    for (int o = 16; o; o >>= 1) m = fmaxf(m, __shfl_xor_sync(~0u, m, o));
    if ((tid & 31) == 0) red_m[tid >> 5] = m;
    __syncthreads();
    m = fmaxf(fmaxf(red_m[0], red_m[1]), fmaxf(red_m[2], red_m[3]));

    float p = expf(s - m);
    pr[tid] = p;
    float sm = p;
#pragma unroll
    for (int o = 16; o; o >>= 1) sm += __shfl_xor_sync(~0u, sm, o);
    if ((tid & 31) == 0) red_s[tid >> 5] = sm;
    __syncthreads();
    float denom = red_s[0] + red_s[1] + red_s[2] + red_s[3] + expf(sinks[h] - m);

    if (tid < HDc) {
        float acc = 0.f;
#pragma unroll 4
        for (int s2 = 0; s2 < 128; s2++) {
            long long vb2 = vbase[s2];
            const float* vp = (vb2 < 0) ? (qkvb + (-vb2 - 1)) : (kvc + vb2);
            acc += pr[s2] * vp[tid];
        }
        attnout[(size_t)t * Hc + h * HDc + tid] = acc / denom;
    }
}

// ============================================================
// Router: rmsnorm(ln2) -> x2, logits, top-2 + softmax weights
// ============================================================
__global__ void router_kernel(const float* __restrict__ ln2,
                              const float* __restrict__ Wr,
                              const float* __restrict__ br) {
    int t = blockIdx.x, tid = threadIdx.x;
    __shared__ float sx[Hc];
    __shared__ float red[8];
    __shared__ float lg[Ec];
    const float* hr = g_h + (size_t)t * Hc;
    float ss = 0.f;
#pragma unroll
    for (int i = 0; i < 4; i++) { float v = hr[tid + 256 * i]; ss += v * v; }
#pragma unroll
    for (int o = 16; o; o >>= 1) ss += __shfl_xor_sync(~0u, ss, o);
    if ((tid & 31) == 0) red[tid >> 5] = ss;
    __syncthreads();
    float tot = 0.f;
#pragma unroll
    for (int i = 0; i < 8; i++) tot += red[i];
    float rinv = rsqrtf(tot * (1.0f / Hc) + EPSc);
#pragma unroll
    for (int i = 0; i < 4; i++) {
        int c = tid + 256 * i;
        float v = hr[c] * ln2[c] * rinv;
        sx[c] = v;
        g_x2[(size_t)t * Hc + c] = v;
    }
    __syncthreads();
    int w = tid >> 5, lane = tid & 31;
    float s = 0.f;
    for (int c = lane; c < Hc; c += 32) s += sx[c] * Wr[c * Ec + w];
#pragma unroll
    for (int o = 16; o; o >>= 1) s += __shfl_xor_sync(~0u, s, o);
    if (lane == 0) lg[w] = s + br[w];
    __syncthreads();
    if (tid == 0) {
        int i0 = 0; float v0 = lg[0];
#pragma unroll
        for (int e = 1; e < Ec; e++) if (lg[e] > v0) { v0 = lg[e]; i0 = e; }
        int i1 = -1; float v1 = -1e30f;
#pragma unroll
        for (int e = 0; e < Ec; e++) {
            if (e == i0) continue;
            if (lg[e] > v1) { v1 = lg[e]; i1 = e; }
        }
        float e1 = expf(v1 - v0);
        g_eidx[t * 2] = i0; g_eidx[t * 2 + 1] = i1;
        g_ewt[t * 2] = 1.0f / (1.0f + e1);
        g_ewt[t * 2 + 1] = e1 / (1.0f + e1);
    }
}

// ============================================================
// Bucket tokens by expert (single block)
// ============================================================
__global__ void bucket_kernel() {
    __shared__ int c1[Ec], c2[Ec], so[Ec];
    int tid = threadIdx.x;
    if (tid < Ec) { c1[tid] = 0; c2[tid] = 0; }
    __syncthreads();
    for (int i = tid; i < Tc * 2; i += blockDim.x) atomicAdd(&c1[g_eidx[i]], 1);
    __syncthreads();
    if (tid == 0) {
        int run = 0;
        for (int e = 0; e < Ec; e++) { so[e] = run; run += c1[e]; }
    }
    __syncthreads();
    if (tid < Ec) { g_cnt[tid] = c1[tid]; g_off[tid] = so[tid]; }
    for (int i = tid; i < Tc * 2; i += blockDim.x) {
        int e = g_eidx[i];
        int r = atomicAdd(&c2[e], 1);
        int slot = so[e] + r;
        g_tok[slot] = i >> 1;
        g_slotof[i] = slot;
    }
}

// ============================================================
// Final combine
// ============================================================
__global__ void combine_kernel(float* __restrict__ out) {
    int t = blockIdx.x, tid = threadIdx.x;
    float w0 = g_ewt[t * 2], w1 = g_ewt[t * 2 + 1];
    int s0 = g_slotof[t * 2], s1 = g_slotof[t * 2 + 1];
#pragma unroll
    for (int i = 0; i < 4; i++) {
        int c = tid + 256 * i;
        out[(size_t)t * Hc + c] = g_h[(size_t)t * Hc + c]
                                + w0 * g_eo[(size_t)s0 * Hc + c]
                                + w1 * g_eo[(size_t)s1 * Hc + c];
    }
}

// ============================================================
extern "C" void kernel_launch(void* const* d_in, const int* in_sizes, int n_in,
                              void* d_out, int out_size) {
    const float* hidden = (const float*)d_in[0];
    const float* kvc    = (const float*)d_in[1];
    const int*   pidx   = (const int*)d_in[3];
    const float* sinks  = (const float*)d_in[4];
    const float* w_qkv  = (const float*)d_in[5];
    const float* b_qkv  = (const float*)d_in[6];
    const float* w_o    = (const float*)d_in[7];
    const float* b_o    = (const float*)d_in[8];
    const float* ln1    = (const float*)d_in[9];
    const float* ln2    = (const float*)d_in[10];
    const float* w_r    = (const float*)d_in[11];
    const float* b_r    = (const float*)d_in[12];
    const float* w_gu   = (const float*)d_in[13];
    const float* b_gu   = (const float*)d_in[14];
    const float* w_d    = (const float*)d_in[15];
    const float* b_d    = (const float*)d_in[16];
    float* out = (float*)d_out;

    void *px, *pq, *pa, *ph;
    cudaGetSymbolAddress(&px, g_xnorm);
    cudaGetSymbolAddress(&pq, g_qkv);
    cudaGetSymbolAddress(&pa, g_attn);
    cudaGetSymbolAddress(&ph, g_h);

    cudaFuncSetAttribute(mma_gemm<0, QKVW>, cudaFuncAttributeMaxDynamicSharedMemorySize, GEMM_SMEM);
    cudaFuncSetAttribute(mma_gemm<1, Hc>, cudaFuncAttributeMaxDynamicSharedMemorySize, GEMM_SMEM);
    cudaFuncSetAttribute(mma_gemm<2, 2 * FFNc>, cudaFuncAttributeMaxDynamicSharedMemorySize, GEMM_SMEM);
    cudaFuncSetAttribute(mma_gemm<3, Hc>, cudaFuncAttributeMaxDynamicSharedMemorySize, GEMM_SMEM);

    // 1) ln1
    rmsnorm1_kernel<<<Tc, 256>>>(hidden, ln1, (float*)px);
    // 2) QKV GEMM (HMMA split-bf16)
    mma_gemm<0, QKVW><<<dim3(QKVW / 128, Tc / 64, 1), 256, GEMM_SMEM>>>(
        (const float*)px, w_qkv, b_qkv, nullptr, (float*)pq);
    // 3) attention
    {
        dim3 g(NQc, Qc, Bc);
        attn_kernel<<<g, 128>>>((const float*)pq, kvc, pidx, sinks, (float*)pa);
    }
    // 4) O proj + residual
    mma_gemm<1, Hc><<<dim3(Hc / 128, Tc / 64, 1), 256, GEMM_SMEM>>>(
        (const float*)pa, w_o, b_o, hidden, (float*)ph);
    // 5) router
    router_kernel<<<Tc, 256>>>(ln2, w_r, b_r);
    // 6) bucket
    bucket_kernel<<<1, 256>>>();
    // 7) gate_up (sparse gathered) + swiglu -> act (bf16 hi/lo)
    mma_gemm<2, 2 * FFNc><<<dim3(2 * FFNc / 128, 16, Ec), 256, GEMM_SMEM>>>(
        nullptr, w_gu, b_gu, nullptr, nullptr);
    // 8) down -> g_eo
    mma_gemm<3, Hc><<<dim3(Hc / 128, 16, Ec), 256, GEMM_SMEM>>>(
        nullptr, w_d, b_d, nullptr, nullptr);
    // 9) combine
    combine_kernel<<<Tc, 256>>>(out);
}

// round 4
// speedup vs baseline: 2.6399x; 1.6760x over previous
#include <cuda_runtime.h>
#include <cuda_bf16.h>
#include <math.h>
#include <stdint.h>

// ---- static problem config ----
namespace {
constexpr int Hc = 1024, HDc = 64, NQc = 16, NKVc = 4, Ec = 8, FFNc = 1024;
constexpr int Bc = 4, Qc = 128, Pc = 8, PSc = 128, Sc = 1024, Tc = 512;
constexpr int QKVW = HDc * (NQc + 2 * NKVc);   // 1536
constexpr float SCALEc = 0.125f;
constexpr float ALPHAc = 1.702f, LIMITc = 7.0f, EPSc = 1e-5f;
// GEMM smem: 3 stages x (AH 8K | AL 8K | BH 16K | BL 16K)
constexpr uint32_t ASZ = 64 * 64 * 2;          // 8192
constexpr uint32_t BSZ = 128 * 64 * 2;         // 16384
constexpr uint32_t STAGE = 2 * ASZ + 2 * BSZ;  // 49152
constexpr int NSTAGE = 3;
constexpr int GEMM_SMEM = NSTAGE * (int)STAGE + 1024;
}

// ---- scratch (static __device__, allocation-free) ----
__device__ float g_qkv[Tc * QKVW];
__device__ float g_h[Tc * Hc];
__device__ __nv_bfloat16 g_xnh[Tc * Hc], g_xnl[Tc * Hc];     // ln1 out split
__device__ __nv_bfloat16 g_ath[Tc * Hc], g_atl[Tc * Hc];     // attn out split
__device__ __nv_bfloat16 g_x2h[Tc * Hc], g_x2l[Tc * Hc];     // ln2 out split
__device__ __nv_bfloat16 g_act_hi[Tc * 2 * FFNc], g_act_lo[Tc * 2 * FFNc];
__device__ float g_eo[Tc * 2 * Hc];
__device__ int   g_eidx[Tc * 2];
__device__ float g_ewt[Tc * 2];
__device__ int   g_cnt[Ec];
__device__ int   g_off[Ec];
__device__ int   g_tok[Tc * 2];
__device__ int   g_slotof[Tc * 2];
// transposed split weights: [n][k] bf16, K = 1024 everywhere
__device__ __nv_bfloat16 g_wqh[QKVW * Hc], g_wql[QKVW * Hc];
__device__ __nv_bfloat16 g_woh[Hc * Hc], g_wol[Hc * Hc];
__device__ __nv_bfloat16 g_wguh[Ec * 2 * FFNc * Hc], g_wgul[Ec * 2 * FFNc * Hc];
__device__ __nv_bfloat16 g_wdh[Ec * Hc * FFNc], g_wdl[Ec * Hc * FFNc];

// ============================================================
__device__ __forceinline__ uint32_t smem_to_u32(const void* p) {
    uint32_t a;
    asm("{ .reg .u64 t; cvta.to.shared.u64 t, %1; cvt.u32.u64 %0, t; }" : "=r"(a) : "l"(p));
    return a;
}
__device__ __forceinline__ void ldm_x4(uint32_t& r0, uint32_t& r1, uint32_t& r2,
                                       uint32_t& r3, uint32_t addr) {
    asm volatile("ldmatrix.sync.aligned.m8n8.x4.shared.b16 {%0,%1,%2,%3}, [%4];"
                 : "=r"(r0), "=r"(r1), "=r"(r2), "=r"(r3) : "r"(addr));
}
__device__ __forceinline__ void mma_bf16(float* c, const uint32_t* a, const uint32_t* b) {
    asm volatile(
        "mma.sync.aligned.m16n8k16.row.col.f32.bf16.bf16.f32 "
        "{%0,%1,%2,%3}, {%4,%5,%6,%7}, {%8,%9}, {%0,%1,%2,%3};"
        : "+f"(c[0]), "+f"(c[1]), "+f"(c[2]), "+f"(c[3])
        : "r"(a[0]), "r"(a[1]), "r"(a[2]), "r"(a[3]), "r"(b[0]), "r"(b[1]));
}
__device__ __forceinline__ void cp16(uint32_t dst, const void* src, bool pred) {
    int sz = pred ? 16 : 0;
    asm volatile("cp.async.cg.shared.global [%0], [%1], 16, %2;"
                 :: "r"(dst), "l"(src), "r"(sz) : "memory");
}
#define CP_COMMIT() asm volatile("cp.async.commit_group;" ::: "memory")

// ============================================================
// Prep: transpose + bf16 hi/lo split.  in: W[z][K][N] fp32 -> out[z][N][K] bf16
// 64x64 tiles, 256 threads
// ============================================================
__global__ void transpose_split_kernel(const float* __restrict__ src,
                                       __nv_bfloat16* __restrict__ dh,
                                       __nv_bfloat16* __restrict__ dl,
                                       int K, int N) {
    __shared__ float tile[64][65];
    int z = blockIdx.z;
    src += (size_t)z * K * N;
    dh += (size_t)z * K * N;
    dl += (size_t)z * K * N;
    int x = blockIdx.x * 64, y = blockIdx.y * 64;   // x: n, y: k
    int t = threadIdx.x;
    int tx = t & 63, ty = t >> 6;  // ty 0..3
#pragma unroll
    for (int j = 0; j < 64; j += 4)
        tile[ty + j][tx] = src[(size_t)(y + ty + j) * N + x + tx];
    __syncthreads();
    int kk = (t & 31) * 2, nn = t >> 5;  // nn 0..7
    uint32_t* dh32 = (uint32_t*)dh;
    uint32_t* dl32 = (uint32_t*)dl;
#pragma unroll
    for (int j = 0; j < 64; j += 8) {
        int n = x + nn + j;
        float v0 = tile[kk][nn + j], v1 = tile[kk + 1][nn + j];
        __nv_bfloat16 h0 = __float2bfloat16(v0), h1 = __float2bfloat16(v1);
        __nv_bfloat16 l0 = __float2bfloat16(v0 - __bfloat162float(h0));
        __nv_bfloat16 l1 = __float2bfloat16(v1 - __bfloat162float(h1));
        size_t ep = ((size_t)n * K + y + kk) >> 1;
        dh32[ep] = ((uint32_t)__bfloat16_as_ushort(h1) << 16) | __bfloat16_as_ushort(h0);
        dl32[ep] = ((uint32_t)__bfloat16_as_ushort(l1) << 16) | __bfloat16_as_ushort(l0);
    }
}

// ============================================================
// HMMA GEMM with cp.async pipeline. C tile 64x128, K=1024 (16 blocks of 64).
// All operands pre-split bf16: A [m][k], B [n][k] (k contiguous).
// MODE: 0=QKV, 1=OPROJ(+resid), 2=GATEUP(gather+swiglu->act), 3=DOWN(->eo)
// ============================================================
template <int MODE, int NN>
__global__ __launch_bounds__(256, 1) void mma_gemm(
    const __nv_bfloat16* __restrict__ Ah, const __nv_bfloat16* __restrict__ Al,
    const __nv_bfloat16* __restrict__ Bh, const __nv_bfloat16* __restrict__ Bl,
    const float* __restrict__ bias, const float* __restrict__ resid,
    float* __restrict__ Cout) {
    extern __shared__ __align__(1024) char dsm[];
    __shared__ int s_tok[64];

    const int tid = threadIdx.x, wid = tid >> 5, lane = tid & 31;
    const int wm = wid & 1, wn = wid >> 1;
    const int e = blockIdx.z;
    const int row0 = blockIdx.y * 64, col0 = blockIdx.x * 128;
    int cnt = Tc, off = 0;
    if (MODE >= 2) {
        cnt = g_cnt[e];
        off = g_off[e];
        if (row0 >= cnt) return;
    }
    const __nv_bfloat16* Bhg = Bh + (MODE >= 2 ? (size_t)e * NN * 1024 : 0);
    const __nv_bfloat16* Blg = Bl + (MODE >= 2 ? (size_t)e * NN * 1024 : 0);

    uint32_t base = (smem_to_u32(dsm) + 1023) & ~1023u;

    if (MODE == 2 && tid < 64) {
        int r = row0 + tid;
        s_tok[tid] = (r < cnt) ? g_tok[off + r] : -1;
    }
    if (MODE == 2) __syncthreads();

    // ---- issue one K-block stage of cp.asyncs ----
    auto issue_stage = [&](int kb, uint32_t buf) {
        const int kbase = kb * 64;
        // A: 64 rows x 64 k; 512 16B-chunks hi + lo
#pragma unroll
        for (int i = 0; i < 2; i++) {
            int c = tid + 256 * i;
            int row = c >> 3, k8 = c & 7;
            uint32_t raw = row * 128 + k8 * 16;
            uint32_t sw = raw ^ ((raw >> 3) & 0x70);
            size_t o;
            bool pred = true;
            if (MODE == 2) {
                int tok = s_tok[row];
                pred = tok >= 0;
                o = (size_t)(pred ? tok : 0) * 1024 + kbase + k8 * 8;
            } else if (MODE == 3) {
                int r = row0 + row;
                pred = r < cnt;
                o = (size_t)(off + (pred ? r : 0)) * 1024 + kbase + k8 * 8;
            } else {
                o = (size_t)(row0 + row) * 1024 + kbase + k8 * 8;
            }
            cp16(buf + sw, Ah + o, pred);
            cp16(buf + ASZ + sw, Al + o, pred);
        }
        // B: 128 rows x 64 k; 1024 chunks hi + lo
#pragma unroll
        for (int i = 0; i < 4; i++) {
            int c = tid + 256 * i;
            int row = c >> 3, k8 = c & 7;
            uint32_t raw = row * 128 + k8 * 16;
            uint32_t sw = raw ^ ((raw >> 3) & 0x70);
            size_t o = (size_t)(col0 + row) * 1024 + kbase + k8 * 8;
            cp16(buf + 2 * ASZ + sw, Bhg + o, true);
            cp16(buf + 2 * ASZ + BSZ + sw, Blg + o, true);
        }
        CP_COMMIT();
    };

    float acc[2][4][4] = {};

    const uint32_t a_raw0 = (uint32_t)(wm * 32 + (lane & 15)) * 128 + (lane >> 4) * 16;
    const int b_grp = lane >> 3;
    const uint32_t b_raw0 =
        (uint32_t)(wn * 32 + ((b_grp >> 1) << 3) + (lane & 7)) * 128 + (b_grp & 1) * 16;

    auto compute = [&](uint32_t buf) {
        uint32_t AH = buf, AL = buf + ASZ, BH = buf + 2 * ASZ, BL = BH + BSZ;
#pragma unroll
        for (int ks = 0; ks < 4; ks++) {
            uint32_t ah[2][4], al[2][4], bh[4][2], bl[4][2];
#pragma unroll
            for (int mi = 0; mi < 2; mi++) {
                uint32_t raw = a_raw0 + mi * 2048 + ks * 32;
                uint32_t sw = raw ^ ((raw >> 3) & 0x70);
                ldm_x4(ah[mi][0], ah[mi][1], ah[mi][2], ah[mi][3], AH + sw);
                ldm_x4(al[mi][0], al[mi][1], al[mi][2], al[mi][3], AL + sw);
            }
#pragma unroll
            for (int np = 0; np < 2; np++) {
                uint32_t raw = b_raw0 + np * 2048 + ks * 32;
                uint32_t sw = raw ^ ((raw >> 3) & 0x70);
                ldm_x4(bh[2 * np][0], bh[2 * np][1], bh[2 * np + 1][0], bh[2 * np + 1][1],
                       BH + sw);
                ldm_x4(bl[2 * np][0], bl[2 * np][1], bl[2 * np + 1][0], bl[2 * np + 1][1],
                       BL + sw);
            }
#pragma unroll
            for (int mi = 0; mi < 2; mi++)
#pragma unroll
                for (int ni = 0; ni < 4; ni++) {
                    mma_bf16(acc[mi][ni], ah[mi], bh[ni]);
                    mma_bf16(acc[mi][ni], ah[mi], bl[ni]);
                    mma_bf16(acc[mi][ni], al[mi], bh[ni]);
                }
        }
    };

    // ---- pipelined mainloop (3-stage) ----
    issue_stage(0, base);
    issue_stage(1, base + STAGE);
    issue_stage(2, base + 2 * STAGE);
    for (int kb = 0; kb < 16; kb++) {
        if (kb < 14)
            asm volatile("cp.async.wait_group 2;" ::: "memory");
        else if (kb == 14)
            asm volatile("cp.async.wait_group 1;" ::: "memory");
        else
            asm volatile("cp.async.wait_group 0;" ::: "memory");
        __syncthreads();
        uint32_t buf = base + (uint32_t)(kb % 3) * STAGE;
        compute(buf);
        __syncthreads();
        if (kb + 3 < 16) issue_stage(kb + 3, buf);
    }

    // ---- epilogue from registers ----
    const int g = lane >> 2, tg = lane & 3;
#pragma unroll
    for (int mi = 0; mi < 2; mi++) {
#pragma unroll
        for (int ni = 0; ni < 4; ni++) {
#pragma unroll
            for (int hh = 0; hh < 2; hh++) {
                int r = row0 + wm * 32 + mi * 16 + g + hh * 8;
                int c = col0 + wn * 32 + ni * 8 + tg * 2;
                float v0 = acc[mi][ni][2 * hh + 0];
                float v1 = acc[mi][ni][2 * hh + 1];
                if (MODE == 0) {
                    size_t p = (size_t)r * NN + c;
                    Cout[p] = v0 + bias[c];
                    Cout[p + 1] = v1 + bias[c + 1];
                } else if (MODE == 1) {
                    size_t p = (size_t)r * NN + c;
                    Cout[p] = v0 + bias[c] + resid[p];
                    Cout[p + 1] = v1 + bias[c + 1] + resid[p + 1];
                } else if (MODE == 2) {
                    if (r < cnt) {
                        const float* bg = bias + (size_t)e * 2 * FFNc;
                        float gv = v0 + bg[c];
                        float uv = v1 + bg[c + 1];
                        gv = fminf(gv, LIMITc);
                        uv = fminf(fmaxf(uv, -LIMITc), LIMITc);
                        float glu = gv / (1.0f + expf(-ALPHAc * gv));
                        float a = (uv + 1.0f) * glu;
                        __nv_bfloat16 h = __float2bfloat16(a);
                        __nv_bfloat16 l = __float2bfloat16(a - __bfloat162float(h));
                        size_t p = (size_t)(off + r) * FFNc + (c >> 1);
                        g_act_hi[p] = h;
                        g_act_lo[p] = l;
                    }
                } else {
                    if (r < cnt) {
                        const float* bd = bias + (size_t)e * Hc;
                        size_t p = (size_t)(off + r) * Hc + c;
                        g_eo[p] = v0 + bd[c];
                        g_eo[p + 1] = v1 + bd[c + 1];
                    }
                }
            }
        }
    }
}

// ============================================================
// RMSNorm (ln1) -> bf16 hi/lo split
// ============================================================
__global__ void rmsnorm1_kernel(const float* __restrict__ x,
                                const float* __restrict__ w) {
    int t = blockIdx.x, tid = threadIdx.x;
    const float* xr = x + (size_t)t * Hc;
    float ss = 0.f;
#pragma unroll
    for (int i = 0; i < 4; i++) { float v = xr[tid + 256 * i]; ss += v * v; }
#pragma unroll
    for (int o = 16; o; o >>= 1) ss += __shfl_xor_sync(~0u, ss, o);
    __shared__ float red[8];
    if ((tid & 31) == 0) red[tid >> 5] = ss;
    __syncthreads();
    float tot = 0.f;
#pragma unroll
    for (int i = 0; i < 8; i++) tot += red[i];
    float rinv = rsqrtf(tot * (1.0f / Hc) + EPSc);
#pragma unroll
    for (int i = 0; i < 4; i++) {
        int c = tid + 256 * i;
        float v = xr[c] * w[c] * rinv;
        __nv_bfloat16 h = __float2bfloat16(v);
        g_xnh[(size_t)t * Hc + c] = h;
        g_xnl[(size_t)t * Hc + c] = __float2bfloat16(v - __bfloat162float(h));
    }
}

// ============================================================
// Windowed GQA attention with sink (window = exactly 128 keys)
// ============================================================
__global__ void attn_kernel(const float* __restrict__ qkvb,
                            const float* __restrict__ kvc,
                            const int* __restrict__ pidx,
                            const float* __restrict__ sinks) {
    int h = blockIdx.x, q = blockIdx.y, b = blockIdx.z;
    int tid = threadIdx.x;
    int t = b * Qc + q;
    int qpos = (Sc - Qc) + q;
    int w0 = qpos - 127;
    int kvh = h >> 2;

    __shared__ float4 qs[HDc / 4];
    __shared__ float pr[128];
    __shared__ long long vbase[128];
    __shared__ float red_m[4], red_s[4];

    if (tid < HDc / 4)
        qs[tid] = make_float4(
            qkvb[(size_t)t * QKVW + h * HDc + 4 * tid + 0] * SCALEc,
            qkvb[(size_t)t * QKVW + h * HDc + 4 * tid + 1] * SCALEc,
            qkvb[(size_t)t * QKVW + h * HDc + 4 * tid + 2] * SCALEc,
            qkvb[(size_t)t * QKVW + h * HDc + 4 * tid + 3] * SCALEc);

    int kpos = w0 + tid;
    const float* kptr;
    long long vb;
    if (kpos >= Sc - Qc) {
        int tt = b * Qc + (kpos - (Sc - Qc));
        long long koff = (long long)tt * QKVW + (NQc + kvh) * HDc;
        long long voff = (long long)tt * QKVW + (NQc + NKVc + kvh) * HDc;
        kptr = qkvb + koff;
        vb = -voff - 1;
    } else {
        int pg = pidx[b * Pc + (kpos >> 7)];
        long long base = (((long long)pg * 2 + 0) * PSc + (kpos & 127)) * (NKVc * HDc) + kvh * HDc;
        kptr = kvc + base;
        vb = base + (long long)PSc * NKVc * HDc;
    }
    vbase[tid] = vb;
    __syncthreads();

    float s = 0.f;
    const float4* k4 = (const float4*)kptr;
#pragma unroll
    for (int d = 0; d < HDc / 4; d++) {
        float4 kv = k4[d];
        float4 qv = qs[d];
        s += qv.x * kv.x + qv.y * kv.y + qv.z * kv.z + qv.w * kv.w;
    }

    float m = s;
#pragma unroll
    for (int o = 16; o; o >>= 1) m = fmaxf(m, __shfl_xor_sync(~0u, m, o));
    if ((tid & 31) == 0) red_m[tid >> 5] = m;
    __syncthreads();
    m = fmaxf(fmaxf(red_m[0], red_m[1]), fmaxf(red_m[2], red_m[3]));

    float p = expf(s - m);
    pr[tid] = p;
    float sm = p;
#pragma unroll
    for (int o = 16; o; o >>= 1) sm += __shfl_xor_sync(~0u, sm, o);
    if ((tid & 31) == 0) red_s[tid >> 5] = sm;
    __syncthreads();
    float denom = red_s[0] + red_s[1] + red_s[2] + red_s[3] + expf(sinks[h] - m);

    if (tid < HDc) {
        float acc = 0.f;
#pragma unroll 4
        for (int s2 = 0; s2 < 128; s2++) {
            long long vb2 = vbase[s2];
            const float* vp = (vb2 < 0) ? (qkvb + (-vb2 - 1)) : (kvc + vb2);
            acc += pr[s2] * vp[tid];
        }
        float v = acc / denom;
        __nv_bfloat16 hh = __float2bfloat16(v);
        size_t p2 = (size_t)t * Hc + h * HDc + tid;
        g_ath[p2] = hh;
        g_atl[p2] = __float2bfloat16(v - __bfloat162float(hh));
    }
}

// ============================================================
// Router: rmsnorm(ln2) -> x2 (bf16 split), logits, top-2 weights
// ============================================================
__global__ void router_kernel(const float* __restrict__ ln2,
                              const float* __restrict__ Wr,
                              const float* __restrict__ br) {
    int t = blockIdx.x, tid = threadIdx.x;
    __shared__ float sx[Hc];
    __shared__ float red[8];
    __shared__ float lg[Ec];
    const float* hr = g_h + (size_t)t * Hc;
    float ss = 0.f;
#pragma unroll
    for (int i = 0; i < 4; i++) { float v = hr[tid + 256 * i]; ss += v * v; }
#pragma unroll
    for (int o = 16; o; o >>= 1) ss += __shfl_xor_sync(~0u, ss, o);
    if ((tid & 31) == 0) red[tid >> 5] = ss;
    __syncthreads();
    float tot = 0.f;
#pragma unroll
    for (int i = 0; i < 8; i++) tot += red[i];
    float rinv = rsqrtf(tot * (1.0f / Hc) + EPSc);
#pragma unroll
    for (int i = 0; i < 4; i++) {
        int c = tid + 256 * i;
        float v = hr[c] * ln2[c] * rinv;
        sx[c] = v;
        __nv_bfloat16 hb = __float2bfloat16(v);
        g_x2h[(size_t)t * Hc + c] = hb;
        g_x2l[(size_t)t * Hc + c] = __float2bfloat16(v - __bfloat162float(hb));
    }
    __syncthreads();
    int w = tid >> 5, lane = tid & 31;
    float s = 0.f;
    for (int c = lane; c < Hc; c += 32) s += sx[c] * Wr[c * Ec + w];
#pragma unroll
    for (int o = 16; o; o >>= 1) s += __shfl_xor_sync(~0u, s, o);
    if (lane == 0) lg[w] = s + br[w];
    __syncthreads();
    if (tid == 0) {
        int i0 = 0; float v0 = lg[0];
#pragma unroll
        for (int e = 1; e < Ec; e++) if (lg[e] > v0) { v0 = lg[e]; i0 = e; }
        int i1 = -1; float v1 = -1e30f;
#pragma unroll
        for (int e = 0; e < Ec; e++) {
            if (e == i0) continue;
            if (lg[e] > v1) { v1 = lg[e]; i1 = e; }
        }
        float e1 = expf(v1 - v0);
        g_eidx[t * 2] = i0; g_eidx[t * 2 + 1] = i1;
        g_ewt[t * 2] = 1.0f / (1.0f + e1);
        g_ewt[t * 2 + 1] = e1 / (1.0f + e1);
    }
}

// ============================================================
// Bucket tokens by expert (single block)
// ============================================================
__global__ void bucket_kernel() {
    __shared__ int c1[Ec], c2[Ec], so[Ec];
    int tid = threadIdx.x;
    if (tid < Ec) { c1[tid] = 0; c2[tid] = 0; }
    __syncthreads();
    for (int i = tid; i < Tc * 2; i += blockDim.x) atomicAdd(&c1[g_eidx[i]], 1);
    __syncthreads();
    if (tid == 0) {
        int run = 0;
        for (int e = 0; e < Ec; e++) { so[e] = run; run += c1[e]; }
    }
    __syncthreads();
    if (tid < Ec) { g_cnt[tid] = c1[tid]; g_off[tid] = so[tid]; }
    for (int i = tid; i < Tc * 2; i += blockDim.x) {
        int e = g_eidx[i];
        int r = atomicAdd(&c2[e], 1);
        int slot = so[e] + r;
        g_tok[slot] = i >> 1;
        g_slotof[i] = slot;
    }
}

// ============================================================
// Final combine
// ============================================================
__global__ void combine_kernel(float* __restrict__ out) {
    int t = blockIdx.x, tid = threadIdx.x;
    float w0 = g_ewt[t * 2], w1 = g_ewt[t * 2 + 1];
    int s0 = g_slotof[t * 2], s1 = g_slotof[t * 2 + 1];
#pragma unroll
    for (int i = 0; i < 4; i++) {
        int c = tid + 256 * i;
        out[(size_t)t * Hc + c] = g_h[(size_t)t * Hc + c]
                                + w0 * g_eo[(size_t)s0 * Hc + c]
                                + w1 * g_eo[(size_t)s1 * Hc + c];
    }
}

// ============================================================
extern "C" void kernel_launch(void* const* d_in, const int* in_sizes, int n_in,
                              void* d_out, int out_size) {
    const float* hidden = (const float*)d_in[0];
    const float* kvc    = (const float*)d_in[1];
    const int*   pidx   = (const int*)d_in[3];
    const float* sinks  = (const float*)d_in[4];
    const float* w_qkv  = (const float*)d_in[5];
    const float* b_qkv  = (const float*)d_in[6];
    const float* w_o    = (const float*)d_in[7];
    const float* b_o    = (const float*)d_in[8];
    const float* ln1    = (const float*)d_in[9];
    const float* ln2    = (const float*)d_in[10];
    const float* w_r    = (const float*)d_in[11];
    const float* b_r    = (const float*)d_in[12];
    const float* w_gu   = (const float*)d_in[13];
    const float* b_gu   = (const float*)d_in[14];
    const float* w_d    = (const float*)d_in[15];
    const float* b_d    = (const float*)d_in[16];
    float* out = (float*)d_out;

    void *pq, *ph;
    void *pxh, *pxl, *pah, *pal, *px2h, *px2l, *pacth, *pactl;
    void *pwqh, *pwql, *pwoh, *pwol, *pwguh, *pwgul, *pwdh, *pwdl;
    cudaGetSymbolAddress(&pq, g_qkv);
    cudaGetSymbolAddress(&ph, g_h);
    cudaGetSymbolAddress(&pxh, g_xnh);  cudaGetSymbolAddress(&pxl, g_xnl);
    cudaGetSymbolAddress(&pah, g_ath);  cudaGetSymbolAddress(&pal, g_atl);
    cudaGetSymbolAddress(&px2h, g_x2h); cudaGetSymbolAddress(&px2l, g_x2l);
    cudaGetSymbolAddress(&pacth, g_act_hi); cudaGetSymbolAddress(&pactl, g_act_lo);
    cudaGetSymbolAddress(&pwqh, g_wqh); cudaGetSymbolAddress(&pwql, g_wql);
    cudaGetSymbolAddress(&pwoh, g_woh); cudaGetSymbolAddress(&pwol, g_wol);
    cudaGetSymbolAddress(&pwguh, g_wguh); cudaGetSymbolAddress(&pwgul, g_wgul);
    cudaGetSymbolAddress(&pwdh, g_wdh);   cudaGetSymbolAddress(&pwdl, g_wdl);

    cudaFuncSetAttribute(mma_gemm<0, QKVW>, cudaFuncAttributeMaxDynamicSharedMemorySize, GEMM_SMEM);
    cudaFuncSetAttribute(mma_gemm<1, Hc>, cudaFuncAttributeMaxDynamicSharedMemorySize, GEMM_SMEM);
    cudaFuncSetAttribute(mma_gemm<2, 2 * FFNc>, cudaFuncAttributeMaxDynamicSharedMemorySize, GEMM_SMEM);
    cudaFuncSetAttribute(mma_gemm<3, Hc>, cudaFuncAttributeMaxDynamicSharedMemorySize, GEMM_SMEM);

    // 0) weight prep: transpose + split
    transpose_split_kernel<<<dim3(QKVW / 64, Hc / 64, 1), 256>>>(
        w_qkv, (__nv_bfloat16*)pwqh, (__nv_bfloat16*)pwql, Hc, QKVW);
    transpose_split_kernel<<<dim3(Hc / 64, Hc / 64, 1), 256>>>(
        w_o, (__nv_bfloat16*)pwoh, (__nv_bfloat16*)pwol, Hc, Hc);
    transpose_split_kernel<<<dim3(2 * FFNc / 64, Hc / 64, Ec), 256>>>(
        w_gu, (__nv_bfloat16*)pwguh, (__nv_bfloat16*)pwgul, Hc, 2 * FFNc);
    transpose_split_kernel<<<dim3(Hc / 64, FFNc / 64, Ec), 256>>>(
        w_d, (__nv_bfloat16*)pwdh, (__nv_bfloat16*)pwdl, FFNc, Hc);

    // 1) ln1 -> split
    rmsnorm1_kernel<<<Tc, 256>>>(hidden, ln1);
    // 2) QKV GEMM
    mma_gemm<0, QKVW><<<dim3(QKVW / 128, Tc / 64, 1), 256, GEMM_SMEM>>>(
        (const __nv_bfloat16*)pxh, (const __nv_bfloat16*)pxl,
        (const __nv_bfloat16*)pwqh, (const __nv_bfloat16*)pwql,
        b_qkv, nullptr, (float*)pq);
    // 3) attention
    {
        dim3 g(NQc, Qc, Bc);
        attn_kernel<<<g, 128>>>((const float*)pq, kvc, pidx, sinks);
    }
    // 4) O proj + residual
    mma_gemm<1, Hc><<<dim3(Hc / 128, Tc / 64, 1), 256, GEMM_SMEM>>>(
        (const __nv_bfloat16*)pah, (const __nv_bfloat16*)pal,
        (const __nv_bfloat16*)pwoh, (const __nv_bfloat16*)pwol,
        b_o, hidden, (float*)ph);
    // 5) router
    router_kernel<<<Tc, 256>>>(ln2, w_r, b_r);
    // 6) bucket
    bucket_kernel<<<1, 256>>>();
    // 7) gate_up + swiglu -> act split
    mma_gemm<2, 2 * FFNc><<<dim3(2 * FFNc / 128, 16, Ec), 256, GEMM_SMEM>>>(
        (const __nv_bfloat16*)px2h, (const __nv_bfloat16*)px2l,
        (const __nv_bfloat16*)pwguh, (const __nv_bfloat16*)pwgul,
        b_gu, nullptr, nullptr);
    // 8) down -> g_eo
    mma_gemm<3, Hc><<<dim3(Hc / 128, 16, Ec), 256, GEMM_SMEM>>>(
        (const __nv_bfloat16*)pacth, (const __nv_bfloat16*)pactl,
        (const __nv_bfloat16*)pwdh, (const __nv_bfloat16*)pwdl,
        b_d, nullptr, nullptr);
    // 9) combine
    combine_kernel<<<Tc, 256>>>(out);
}

// round 5
// speedup vs baseline: 2.7541x; 1.0432x over previous
#include <cuda_runtime.h>
#include <cuda_bf16.h>
#include <math.h>
#include <stdint.h>

// ---- static problem config ----
namespace {
constexpr int Hc = 1024, HDc = 64, NQc = 16, NKVc = 4, Ec = 8, FFNc = 1024;
constexpr int Bc = 4, Qc = 128, Pc = 8, PSc = 128, Sc = 1024, Tc = 512;
constexpr int QKVW = HDc * (NQc + 2 * NKVc);   // 1536
constexpr float SCALEc = 0.125f;
constexpr float ALPHAc = 1.702f, LIMITc = 7.0f, EPSc = 1e-5f;
// GEMM smem: 3 stages x (AH 8K | AL 8K | BH 8K | BL 8K) = 96KB -> 2 CTAs/SM
constexpr uint32_t ASZ = 64 * 64 * 2;          // 8192
constexpr uint32_t BSZ = 64 * 64 * 2;          // 8192
constexpr uint32_t STAGE = 2 * ASZ + 2 * BSZ;  // 32768
constexpr int NSTAGE = 3;
constexpr int GEMM_SMEM = NSTAGE * (int)STAGE + 1024;
}

// ---- scratch (static __device__, allocation-free) ----
__device__ float g_qkv[Tc * QKVW];
__device__ float g_h[Tc * Hc];
__device__ __nv_bfloat16 g_xnh[Tc * Hc], g_xnl[Tc * Hc];
__device__ __nv_bfloat16 g_ath[Tc * Hc], g_atl[Tc * Hc];
__device__ __nv_bfloat16 g_x2h[Tc * Hc], g_x2l[Tc * Hc];
__device__ __nv_bfloat16 g_act_hi[Tc * 2 * FFNc], g_act_lo[Tc * 2 * FFNc];
__device__ float g_eo[Tc * 2 * Hc];
__device__ int   g_eidx[Tc * 2];
__device__ float g_ewt[Tc * 2];
__device__ int   g_cnt[Ec];
__device__ int   g_off[Ec];
__device__ int   g_tok[Tc * 2];
__device__ int   g_slotof[Tc * 2];
// transposed split weights: [n][k] bf16, K = 1024 everywhere
__device__ __nv_bfloat16 g_wqh[QKVW * Hc], g_wql[QKVW * Hc];
__device__ __nv_bfloat16 g_woh[Hc * Hc], g_wol[Hc * Hc];
__device__ __nv_bfloat16 g_wguh[Ec * 2 * FFNc * Hc], g_wgul[Ec * 2 * FFNc * Hc];
__device__ __nv_bfloat16 g_wdh[Ec * Hc * FFNc], g_wdl[Ec * Hc * FFNc];

// ============================================================
__device__ __forceinline__ uint32_t smem_to_u32(const void* p) {
    uint32_t a;
    asm("{ .reg .u64 t; cvta.to.shared.u64 t, %1; cvt.u32.u64 %0, t; }" : "=r"(a) : "l"(p));
    return a;
}
__device__ __forceinline__ void ldm_x4(uint32_t& r0, uint32_t& r1, uint32_t& r2,
                                       uint32_t& r3, uint32_t addr) {
    asm volatile("ldmatrix.sync.aligned.m8n8.x4.shared.b16 {%0,%1,%2,%3}, [%4];"
                 : "=r"(r0), "=r"(r1), "=r"(r2), "=r"(r3) : "r"(addr));
}
__device__ __forceinline__ void mma_bf16(float* c, const uint32_t* a, const uint32_t* b) {
    asm volatile(
        "mma.sync.aligned.m16n8k16.row.col.f32.bf16.bf16.f32 "
        "{%0,%1,%2,%3}, {%4,%5,%6,%7}, {%8,%9}, {%0,%1,%2,%3};"
        : "+f"(c[0]), "+f"(c[1]), "+f"(c[2]), "+f"(c[3])
        : "r"(a[0]), "r"(a[1]), "r"(a[2]), "r"(a[3]), "r"(b[0]), "r"(b[1]));
}
__device__ __forceinline__ void cp16(uint32_t dst, const void* src, bool pred) {
    int sz = pred ? 16 : 0;
    asm volatile("cp.async.cg.shared.global [%0], [%1], 16, %2;"
                 :: "r"(dst), "l"(src), "r"(sz) : "memory");
}
#define CP_COMMIT() asm volatile("cp.async.commit_group;" ::: "memory")

// ============================================================
// Prep: transpose + bf16 hi/lo split.  in: W[z][K][N] fp32 -> out[z][N][K] bf16
// ============================================================
__global__ void transpose_split_kernel(const float* __restrict__ src,
                                       __nv_bfloat16* __restrict__ dh,
                                       __nv_bfloat16* __restrict__ dl,
                                       int K, int N) {
    __shared__ float tile[64][65];
    int z = blockIdx.z;
    src += (size_t)z * K * N;
    dh += (size_t)z * K * N;
    dl += (size_t)z * K * N;
    int x = blockIdx.x * 64, y = blockIdx.y * 64;
    int t = threadIdx.x;
    int tx = t & 63, ty = t >> 6;
#pragma unroll
    for (int j = 0; j < 64; j += 4)
        tile[ty + j][tx] = src[(size_t)(y + ty + j) * N + x + tx];
    __syncthreads();
    int kk = (t & 31) * 2, nn = t >> 5;
    uint32_t* dh32 = (uint32_t*)dh;
    uint32_t* dl32 = (uint32_t*)dl;
#pragma unroll
    for (int j = 0; j < 64; j += 8) {
        int n = x + nn + j;
        float v0 = tile[kk][nn + j], v1 = tile[kk + 1][nn + j];
        __nv_bfloat16 h0 = __float2bfloat16(v0), h1 = __float2bfloat16(v1);
        __nv_bfloat16 l0 = __float2bfloat16(v0 - __bfloat162float(h0));
        __nv_bfloat16 l1 = __float2bfloat16(v1 - __bfloat162float(h1));
        size_t ep = ((size_t)n * K + y + kk) >> 1;
        dh32[ep] = ((uint32_t)__bfloat16_as_ushort(h1) << 16) | __bfloat16_as_ushort(h0);
        dl32[ep] = ((uint32_t)__bfloat16_as_ushort(l1) << 16) | __bfloat16_as_ushort(l0);
    }
}

// ============================================================
// HMMA GEMM, 64x64 C tile, K=1024 (16 blocks of 64), split-bf16 (3 MMA),
// 3-stage cp.async pipeline, 2 CTAs/SM.
// MODE: 0=QKV, 1=OPROJ(+resid), 2=GATEUP(gather+swiglu->act), 3=DOWN(->eo)
// ============================================================
template <int MODE, int NN>
__global__ __launch_bounds__(256, 2) void mma_gemm(
    const __nv_bfloat16* __restrict__ Ah, const __nv_bfloat16* __restrict__ Al,
    const __nv_bfloat16* __restrict__ Bh, const __nv_bfloat16* __restrict__ Bl,
    const float* __restrict__ bias, const float* __restrict__ resid,
    float* __restrict__ Cout) {
    extern __shared__ __align__(1024) char dsm[];
    __shared__ int s_tok[64];

    const int tid = threadIdx.x, wid = tid >> 5, lane = tid & 31;
    const int wm = wid & 1, wn = wid >> 1;          // 2 x 4 warp grid
    const int e = blockIdx.z;
    const int row0 = blockIdx.y * 64, col0 = blockIdx.x * 64;
    int cnt = Tc, off = 0;
    if (MODE >= 2) {
        cnt = g_cnt[e];
        off = g_off[e];
        if (row0 >= cnt) return;
    }
    const __nv_bfloat16* Bhg = Bh + (MODE >= 2 ? (size_t)e * NN * 1024 : 0);
    const __nv_bfloat16* Blg = Bl + (MODE >= 2 ? (size_t)e * NN * 1024 : 0);

    uint32_t base = (smem_to_u32(dsm) + 1023) & ~1023u;

    if (MODE == 2 && tid < 64) {
        int r = row0 + tid;
        s_tok[tid] = (r < cnt) ? g_tok[off + r] : -1;
    }
    if (MODE == 2) __syncthreads();

    // ---- issue one K-block stage: A 64x64, B 64x64, hi+lo ----
    auto issue_stage = [&](int kb, uint32_t buf) {
        const int kbase = kb * 64;
#pragma unroll
        for (int i = 0; i < 2; i++) {
            int c = tid + 256 * i;
            int row = c >> 3, k8 = c & 7;
            uint32_t raw = row * 128 + k8 * 16;
            uint32_t sw = raw ^ ((raw >> 3) & 0x70);
            size_t o;
            bool pred = true;
            if (MODE == 2) {
                int tok = s_tok[row];
                pred = tok >= 0;
                o = (size_t)(pred ? tok : 0) * 1024 + kbase + k8 * 8;
            } else if (MODE == 3) {
                int r = row0 + row;
                pred = r < cnt;
                o = (size_t)(off + (pred ? r : 0)) * 1024 + kbase + k8 * 8;
            } else {
                o = (size_t)(row0 + row) * 1024 + kbase + k8 * 8;
            }
            cp16(buf + sw, Ah + o, pred);
            cp16(buf + ASZ + sw, Al + o, pred);
        }
#pragma unroll
        for (int i = 0; i < 2; i++) {
            int c = tid + 256 * i;
            int row = c >> 3, k8 = c & 7;
            uint32_t raw = row * 128 + k8 * 16;
            uint32_t sw = raw ^ ((raw >> 3) & 0x70);
            size_t o = (size_t)(col0 + row) * 1024 + kbase + k8 * 8;
            cp16(buf + 2 * ASZ + sw, Bhg + o, true);
            cp16(buf + 2 * ASZ + BSZ + sw, Blg + o, true);
        }
        CP_COMMIT();
    };

    float acc[2][2][4] = {};

    const uint32_t a_raw0 = (uint32_t)(wm * 32 + (lane & 15)) * 128 + (lane >> 4) * 16;
    const int b_grp = lane >> 3;
    const uint32_t b_raw0 =
        (uint32_t)(wn * 16 + ((b_grp >> 1) << 3) + (lane & 7)) * 128 + (b_grp & 1) * 16;

    auto compute = [&](uint32_t buf) {
        uint32_t AH = buf, AL = buf + ASZ, BH = buf + 2 * ASZ, BL = BH + BSZ;
#pragma unroll
        for (int ks = 0; ks < 4; ks++) {
            uint32_t ah[2][4], al[2][4], bh[2][2], bl[2][2];
#pragma unroll
            for (int mi = 0; mi < 2; mi++) {
                uint32_t raw = a_raw0 + mi * 2048 + ks * 32;
                uint32_t sw = raw ^ ((raw >> 3) & 0x70);
                ldm_x4(ah[mi][0], ah[mi][1], ah[mi][2], ah[mi][3], AH + sw);
                ldm_x4(al[mi][0], al[mi][1], al[mi][2], al[mi][3], AL + sw);
            }
            {
                uint32_t raw = b_raw0 + ks * 32;
                uint32_t sw = raw ^ ((raw >> 3) & 0x70);
                ldm_x4(bh[0][0], bh[0][1], bh[1][0], bh[1][1], BH + sw);
                ldm_x4(bl[0][0], bl[0][1], bl[1][0], bl[1][1], BL + sw);
            }
#pragma unroll
            for (int mi = 0; mi < 2; mi++)
#pragma unroll
                for (int ni = 0; ni < 2; ni++) {
                    mma_bf16(acc[mi][ni], ah[mi], bh[ni]);
                    mma_bf16(acc[mi][ni], ah[mi], bl[ni]);
                    mma_bf16(acc[mi][ni], al[mi], bh[ni]);
                }
        }
    };

    issue_stage(0, base);
    issue_stage(1, base + STAGE);
    issue_stage(2, base + 2 * STAGE);
    for (int kb = 0; kb < 16; kb++) {
        if (kb < 14)
            asm volatile("cp.async.wait_group 2;" ::: "memory");
        else if (kb == 14)
            asm volatile("cp.async.wait_group 1;" ::: "memory");
        else
            asm volatile("cp.async.wait_group 0;" ::: "memory");
        __syncthreads();
        uint32_t buf = base + (uint32_t)(kb % 3) * STAGE;
        compute(buf);
        __syncthreads();
        if (kb + 3 < 16) issue_stage(kb + 3, buf);
    }

    // ---- epilogue ----
    const int g = lane >> 2, tg = lane & 3;
#pragma unroll
    for (int mi = 0; mi < 2; mi++) {
#pragma unroll
        for (int ni = 0; ni < 2; ni++) {
#pragma unroll
            for (int hh = 0; hh < 2; hh++) {
                int r = row0 + wm * 32 + mi * 16 + g + hh * 8;
                int c = col0 + wn * 16 + ni * 8 + tg * 2;
                float v0 = acc[mi][ni][2 * hh + 0];
                float v1 = acc[mi][ni][2 * hh + 1];
                if (MODE == 0) {
                    size_t p = (size_t)r * NN + c;
                    Cout[p] = v0 + bias[c];
                    Cout[p + 1] = v1 + bias[c + 1];
                } else if (MODE == 1) {
                    size_t p = (size_t)r * NN + c;
                    Cout[p] = v0 + bias[c] + resid[p];
                    Cout[p + 1] = v1 + bias[c + 1] + resid[p + 1];
                } else if (MODE == 2) {
                    if (r < cnt) {
                        const float* bg = bias + (size_t)e * 2 * FFNc;
                        float gv = v0 + bg[c];
                        float uv = v1 + bg[c + 1];
                        gv = fminf(gv, LIMITc);
                        uv = fminf(fmaxf(uv, -LIMITc), LIMITc);
                        float glu = gv / (1.0f + expf(-ALPHAc * gv));
                        float a = (uv + 1.0f) * glu;
                        __nv_bfloat16 h = __float2bfloat16(a);
                        __nv_bfloat16 l = __float2bfloat16(a - __bfloat162float(h));
                        size_t p = (size_t)(off + r) * FFNc + (c >> 1);
                        g_act_hi[p] = h;
                        g_act_lo[p] = l;
                    }
                } else {
                    if (r < cnt) {
                        const float* bd = bias + (size_t)e * Hc;
                        size_t p = (size_t)(off + r) * Hc + c;
                        g_eo[p] = v0 + bd[c];
                        g_eo[p + 1] = v1 + bd[c + 1];
                    }
                }
            }
        }
    }
}

// ============================================================
// RMSNorm (ln1) -> bf16 hi/lo split
// ============================================================
__global__ void rmsnorm1_kernel(const float* __restrict__ x,
                                const float* __restrict__ w) {
    int t = blockIdx.x, tid = threadIdx.x;
    const float* xr = x + (size_t)t * Hc;
    float ss = 0.f;
#pragma unroll
    for (int i = 0; i < 4; i++) { float v = xr[tid + 256 * i]; ss += v * v; }
#pragma unroll
    for (int o = 16; o; o >>= 1) ss += __shfl_xor_sync(~0u, ss, o);
    __shared__ float red[8];
    if ((tid & 31) == 0) red[tid >> 5] = ss;
    __syncthreads();
    float tot = 0.f;
#pragma unroll
    for (int i = 0; i < 8; i++) tot += red[i];
    float rinv = rsqrtf(tot * (1.0f / Hc) + EPSc);
#pragma unroll
    for (int i = 0; i < 4; i++) {
        int c = tid + 256 * i;
        float v = xr[c] * w[c] * rinv;
        __nv_bfloat16 h = __float2bfloat16(v);
        g_xnh[(size_t)t * Hc + c] = h;
        g_xnl[(size_t)t * Hc + c] = __float2bfloat16(v - __bfloat162float(h));
    }
}

// ============================================================
// Windowed GQA attention with sink (window = exactly 128 keys)
// ============================================================
__global__ void attn_kernel(const float* __restrict__ qkvb,
                            const float* __restrict__ kvc,
                            const int* __restrict__ pidx,
                            const float* __restrict__ sinks) {
    int h = blockIdx.x, q = blockIdx.y, b = blockIdx.z;
    int tid = threadIdx.x;
    int t = b * Qc + q;
    int qpos = (Sc - Qc) + q;
    int w0 = qpos - 127;
    int kvh = h >> 2;

    __shared__ float4 qs[HDc / 4];
    __shared__ float pr[128];
    __shared__ long long vbase[128];
    __shared__ float red_m[4], red_s[4];

    if (tid < HDc / 4)
        qs[tid] = make_float4(
            qkvb[(size_t)t * QKVW + h * HDc + 4 * tid + 0] * SCALEc,
            qkvb[(size_t)t * QKVW + h * HDc + 4 * tid + 1] * SCALEc,
            qkvb[(size_t)t * QKVW + h * HDc + 4 * tid + 2] * SCALEc,
            qkvb[(size_t)t * QKVW + h * HDc + 4 * tid + 3] * SCALEc);

    int kpos = w0 + tid;
    const float* kptr;
    long long vb;
    if (kpos >= Sc - Qc) {
        int tt = b * Qc + (kpos - (Sc - Qc));
        long long koff = (long long)tt * QKVW + (NQc + kvh) * HDc;
        long long voff = (long long)tt * QKVW + (NQc + NKVc + kvh) * HDc;
        kptr = qkvb + koff;
        vb = -voff - 1;
    } else {
        int pg = pidx[b * Pc + (kpos >> 7)];
        long long base = (((long long)pg * 2 + 0) * PSc + (kpos & 127)) * (NKVc * HDc) + kvh * HDc;
        kptr = kvc + base;
        vb = base + (long long)PSc * NKVc * HDc;
    }
    vbase[tid] = vb;
    __syncthreads();

    float s = 0.f;
    const float4* k4 = (const float4*)kptr;
#pragma unroll
    for (int d = 0; d < HDc / 4; d++) {
        float4 kv = k4[d];
        float4 qv = qs[d];
        s += qv.x * kv.x + qv.y * kv.y + qv.z * kv.z + qv.w * kv.w;
    }

    float m = s;
#pragma unroll
    for (int o = 16; o; o >>= 1) m = fmaxf(m, __shfl_xor_sync(~0u, m, o));
    if ((tid & 31) == 0) red_m[tid >> 5] = m;
    __syncthreads();
    m = fmaxf(fmaxf(red_m[0], red_m[1]), fmaxf(red_m[2], red_m[3]));

    float p = expf(s - m);
    pr[tid] = p;
    float sm = p;
#pragma unroll
    for (int o = 16; o; o >>= 1) sm += __shfl_xor_sync(~0u, sm, o);
    if ((tid & 31) == 0) red_s[tid >> 5] = sm;
    __syncthreads();
    float denom = red_s[0] + red_s[1] + red_s[2] + red_s[3] + expf(sinks[h] - m);

    if (tid < HDc) {
        float acc = 0.f;
#pragma unroll 4
        for (int s2 = 0; s2 < 128; s2++) {
            long long vb2 = vbase[s2];
            const float* vp = (vb2 < 0) ? (qkvb + (-vb2 - 1)) : (kvc + vb2);
            acc += pr[s2] * vp[tid];
        }
        float v = acc / denom;
        __nv_bfloat16 hh = __float2bfloat16(v);
        size_t p2 = (size_t)t * Hc + h * HDc + tid;
        g_ath[p2] = hh;
        g_atl[p2] = __float2bfloat16(v - __bfloat162float(hh));
    }
}

// ============================================================
// Router: rmsnorm(ln2) -> x2 (bf16 split), logits, top-2 weights
// ============================================================
__global__ void router_kernel(const float* __restrict__ ln2,
                              const float* __restrict__ Wr,
                              const float* __restrict__ br) {
    int t = blockIdx.x, tid = threadIdx.x;
    __shared__ float sx[Hc];
    __shared__ float red[8];
    __shared__ float lg[Ec];
    const float* hr = g_h + (size_t)t * Hc;
    float ss = 0.f;
#pragma unroll
    for (int i = 0; i < 4; i++) { float v = hr[tid + 256 * i]; ss += v * v; }
#pragma unroll
    for (int o = 16; o; o >>= 1) ss += __shfl_xor_sync(~0u, ss, o);
    if ((tid & 31) == 0) red[tid >> 5] = ss;
    __syncthreads();
    float tot = 0.f;
#pragma unroll
    for (int i = 0; i < 8; i++) tot += red[i];
    float rinv = rsqrtf(tot * (1.0f / Hc) + EPSc);
#pragma unroll
    for (int i = 0; i < 4; i++) {
        int c = tid + 256 * i;
        float v = hr[c] * ln2[c] * rinv;
        sx[c] = v;
        __nv_bfloat16 hb = __float2bfloat16(v);
        g_x2h[(size_t)t * Hc + c] = hb;
        g_x2l[(size_t)t * Hc + c] = __float2bfloat16(v - __bfloat162float(hb));
    }
    __syncthreads();
    int w = tid >> 5, lane = tid & 31;
    float s = 0.f;
    for (int c = lane; c < Hc; c += 32) s += sx[c] * Wr[c * Ec + w];
#pragma unroll
    for (int o = 16; o; o >>= 1) s += __shfl_xor_sync(~0u, s, o);
    if (lane == 0) lg[w] = s + br[w];
    __syncthreads();
    if (tid == 0) {
        int i0 = 0; float v0 = lg[0];
#pragma unroll
        for (int e = 1; e < Ec; e++) if (lg[e] > v0) { v0 = lg[e]; i0 = e; }
        int i1 = -1; float v1 = -1e30f;
#pragma unroll
        for (int e = 0; e < Ec; e++) {
            if (e == i0) continue;
            if (lg[e] > v1) { v1 = lg[e]; i1 = e; }
        }
        float e1 = expf(v1 - v0);
        g_eidx[t * 2] = i0; g_eidx[t * 2 + 1] = i1;
        g_ewt[t * 2] = 1.0f / (1.0f + e1);
        g_ewt[t * 2 + 1] = e1 / (1.0f + e1);
    }
}

// ============================================================
// Bucket tokens by expert (single block)
// ============================================================
__global__ void bucket_kernel() {
    __shared__ int c1[Ec], c2[Ec], so[Ec];
    int tid = threadIdx.x;
    if (tid < Ec) { c1[tid] = 0; c2[tid] = 0; }
    __syncthreads();
    for (int i = tid; i < Tc * 2; i += blockDim.x) atomicAdd(&c1[g_eidx[i]], 1);
    __syncthreads();
    if (tid == 0) {
        int run = 0;
        for (int e = 0; e < Ec; e++) { so[e] = run; run += c1[e]; }
    }
    __syncthreads();
    if (tid < Ec) { g_cnt[tid] = c1[tid]; g_off[tid] = so[tid]; }
    for (int i = tid; i < Tc * 2; i += blockDim.x) {
        int e = g_eidx[i];
        int r = atomicAdd(&c2[e], 1);
        int slot = so[e] + r;
        g_tok[slot] = i >> 1;
        g_slotof[i] = slot;
    }
}

// ============================================================
// Final combine
// ============================================================
__global__ void combine_kernel(float* __restrict__ out) {
    int t = blockIdx.x, tid = threadIdx.x;
    float w0 = g_ewt[t * 2], w1 = g_ewt[t * 2 + 1];
    int s0 = g_slotof[t * 2], s1 = g_slotof[t * 2 + 1];
#pragma unroll
    for (int i = 0; i < 4; i++) {
        int c = tid + 256 * i;
        out[(size_t)t * Hc + c] = g_h[(size_t)t * Hc + c]
                                + w0 * g_eo[(size_t)s0 * Hc + c]
                                + w1 * g_eo[(size_t)s1 * Hc + c];
    }
}

// ============================================================
extern "C" void kernel_launch(void* const* d_in, const int* in_sizes, int n_in,
                              void* d_out, int out_size) {
    const float* hidden = (const float*)d_in[0];
    const float* kvc    = (const float*)d_in[1];
    const int*   pidx   = (const int*)d_in[3];
    const float* sinks  = (const float*)d_in[4];
    const float* w_qkv  = (const float*)d_in[5];
    const float* b_qkv  = (const float*)d_in[6];
    const float* w_o    = (const float*)d_in[7];
    const float* b_o    = (const float*)d_in[8];
    const float* ln1    = (const float*)d_in[9];
    const float* ln2    = (const float*)d_in[10];
    const float* w_r    = (const float*)d_in[11];
    const float* b_r    = (const float*)d_in[12];
    const float* w_gu   = (const float*)d_in[13];
    const float* b_gu   = (const float*)d_in[14];
    const float* w_d    = (const float*)d_in[15];
    const float* b_d    = (const float*)d_in[16];
    float* out = (float*)d_out;

    void *pq, *ph;
    void *pxh, *pxl, *pah, *pal, *px2h, *px2l, *pacth, *pactl;
    void *pwqh, *pwql, *pwoh, *pwol, *pwguh, *pwgul, *pwdh, *pwdl;
    cudaGetSymbolAddress(&pq, g_qkv);
    cudaGetSymbolAddress(&ph, g_h);
    cudaGetSymbolAddress(&pxh, g_xnh);  cudaGetSymbolAddress(&pxl, g_xnl);
    cudaGetSymbolAddress(&pah, g_ath);  cudaGetSymbolAddress(&pal, g_atl);
    cudaGetSymbolAddress(&px2h, g_x2h); cudaGetSymbolAddress(&px2l, g_x2l);
    cudaGetSymbolAddress(&pacth, g_act_hi); cudaGetSymbolAddress(&pactl, g_act_lo);
    cudaGetSymbolAddress(&pwqh, g_wqh); cudaGetSymbolAddress(&pwql, g_wql);
    cudaGetSymbolAddress(&pwoh, g_woh); cudaGetSymbolAddress(&pwol, g_wol);
    cudaGetSymbolAddress(&pwguh, g_wguh); cudaGetSymbolAddress(&pwgul, g_wgul);
    cudaGetSymbolAddress(&pwdh, g_wdh);   cudaGetSymbolAddress(&pwdl, g_wdl);

    cudaFuncSetAttribute(mma_gemm<0, QKVW>, cudaFuncAttributeMaxDynamicSharedMemorySize, GEMM_SMEM);
    cudaFuncSetAttribute(mma_gemm<1, Hc>, cudaFuncAttributeMaxDynamicSharedMemorySize, GEMM_SMEM);
    cudaFuncSetAttribute(mma_gemm<2, 2 * FFNc>, cudaFuncAttributeMaxDynamicSharedMemorySize, GEMM_SMEM);
    cudaFuncSetAttribute(mma_gemm<3, Hc>, cudaFuncAttributeMaxDynamicSharedMemorySize, GEMM_SMEM);

    // 0) weight prep: transpose + split
    transpose_split_kernel<<<dim3(QKVW / 64, Hc / 64, 1), 256>>>(
        w_qkv, (__nv_bfloat16*)pwqh, (__nv_bfloat16*)pwql, Hc, QKVW);
    transpose_split_kernel<<<dim3(Hc / 64, Hc / 64, 1), 256>>>(
        w_o, (__nv_bfloat16*)pwoh, (__nv_bfloat16*)pwol, Hc, Hc);
    transpose_split_kernel<<<dim3(2 * FFNc / 64, Hc / 64, Ec), 256>>>(
        w_gu, (__nv_bfloat16*)pwguh, (__nv_bfloat16*)pwgul, Hc, 2 * FFNc);
    transpose_split_kernel<<<dim3(Hc / 64, FFNc / 64, Ec), 256>>>(
        w_d, (__nv_bfloat16*)pwdh, (__nv_bfloat16*)pwdl, FFNc, Hc);

    // 1) ln1 -> split
    rmsnorm1_kernel<<<Tc, 256>>>(hidden, ln1);
    // 2) QKV GEMM
    mma_gemm<0, QKVW><<<dim3(QKVW / 64, Tc / 64, 1), 256, GEMM_SMEM>>>(
        (const __nv_bfloat16*)pxh, (const __nv_bfloat16*)pxl,
        (const __nv_bfloat16*)pwqh, (const __nv_bfloat16*)pwql,
        b_qkv, nullptr, (float*)pq);
    // 3) attention
    {
        dim3 g(NQc, Qc, Bc);
        attn_kernel<<<g, 128>>>((const float*)pq, kvc, pidx, sinks);
    }
    // 4) O proj + residual
    mma_gemm<1, Hc><<<dim3(Hc / 64, Tc / 64, 1), 256, GEMM_SMEM>>>(
        (const __nv_bfloat16*)pah, (const __nv_bfloat16*)pal,
        (const __nv_bfloat16*)pwoh, (const __nv_bfloat16*)pwol,
        b_o, hidden, (float*)ph);
    // 5) router
    router_kernel<<<Tc, 256>>>(ln2, w_r, b_r);
    // 6) bucket
    bucket_kernel<<<1, 256>>>();
    // 7) gate_up + swiglu -> act split
    mma_gemm<2, 2 * FFNc><<<dim3(2 * FFNc / 64, 16, Ec), 256, GEMM_SMEM>>>(
        (const __nv_bfloat16*)px2h, (const __nv_bfloat16*)px2l,
        (const __nv_bfloat16*)pwguh, (const __nv_bfloat16*)pwgul,
        b_gu, nullptr, nullptr);
    // 8) down -> g_eo
    mma_gemm<3, Hc><<<dim3(Hc / 64, 16, Ec), 256, GEMM_SMEM>>>(
        (const __nv_bfloat16*)pacth, (const __nv_bfloat16*)pactl,
        (const __nv_bfloat16*)pwdh, (const __nv_bfloat16*)pwdl,
        b_d, nullptr, nullptr);
    // 9) combine
    combine_kernel<<<Tc, 256>>>(out);
}

// round 6
// speedup vs baseline: 4.0121x; 1.4568x over previous
#include <cuda_runtime.h>
#include <cuda_bf16.h>
#include <math.h>
#include <stdint.h>

// ---- static problem config ----
namespace {
constexpr int Hc = 1024, HDc = 64, NQc = 16, NKVc = 4, Ec = 8, FFNc = 1024;
constexpr int Bc = 4, Qc = 128, Pc = 8, PSc = 128, Sq = 1024, Tc = 512;
constexpr int QKVW = HDc * (NQc + 2 * NKVc);   // 1536
constexpr float SCALEc = 0.125f;
constexpr float ALPHAc = 1.702f, LIMITc = 7.0f, EPSc = 1e-5f;
// GEMM smem: 3 stages x (AH 8K | AL 8K | BH 8K | BL 8K) = 96KB -> 2 CTAs/SM
constexpr uint32_t ASZ = 64 * 64 * 2;
constexpr uint32_t BSZ = 64 * 64 * 2;
constexpr uint32_t STAGE = 2 * ASZ + 2 * BSZ;  // 32768
constexpr int NSTAGE = 3;
constexpr int GEMM_SMEM = NSTAGE * (int)STAGE + 1024;
// attention smem (floats): K[144][68] V[144][68] Q[4*16*64] S[16*128*4] R[64]
constexpr int AT_KV = 144 * 68;
constexpr int AT_Q = 4 * 16 * 64;
constexpr int AT_S = 16 * 128 * 4;
constexpr int ATT_SMEM = (2 * AT_KV + AT_Q + AT_S + 64) * 4;
}

// ---- scratch (static __device__, allocation-free) ----
__device__ float g_qkv[Tc * QKVW];
__device__ float g_h[Tc * Hc];
__device__ __nv_bfloat16 g_xnh[Tc * Hc], g_xnl[Tc * Hc];
__device__ __nv_bfloat16 g_ath[Tc * Hc], g_atl[Tc * Hc];
__device__ __nv_bfloat16 g_x2h[Tc * Hc], g_x2l[Tc * Hc];
__device__ __nv_bfloat16 g_act_hi[Tc * 2 * FFNc], g_act_lo[Tc * 2 * FFNc];
__device__ float g_eo[Tc * 2 * Hc];
__device__ int   g_eidx[Tc * 2];
__device__ float g_ewt[Tc * 2];
__device__ int   g_cnt[Ec];
__device__ int   g_off[Ec];
__device__ int   g_tok[Tc * 2];
__device__ int   g_slotof[Tc * 2];
// split weights, native [K][N] layout, bf16 hi/lo
__device__ __nv_bfloat16 g_wqh[Hc * QKVW], g_wql[Hc * QKVW];
__device__ __nv_bfloat16 g_woh[Hc * Hc], g_wol[Hc * Hc];
__device__ __nv_bfloat16 g_wguh[Ec * Hc * 2 * FFNc], g_wgul[Ec * Hc * 2 * FFNc];
__device__ __nv_bfloat16 g_wdh[Ec * FFNc * Hc], g_wdl[Ec * FFNc * Hc];

// ============================================================
__device__ __forceinline__ uint32_t smem_to_u32(const void* p) {
    uint32_t a;
    asm("{ .reg .u64 t; cvta.to.shared.u64 t, %1; cvt.u32.u64 %0, t; }" : "=r"(a) : "l"(p));
    return a;
}
__device__ __forceinline__ void ldm_x4(uint32_t& r0, uint32_t& r1, uint32_t& r2,
                                       uint32_t& r3, uint32_t addr) {
    asm volatile("ldmatrix.sync.aligned.m8n8.x4.shared.b16 {%0,%1,%2,%3}, [%4];"
                 : "=r"(r0), "=r"(r1), "=r"(r2), "=r"(r3) : "r"(addr));
}
__device__ __forceinline__ void ldm_x4_t(uint32_t& r0, uint32_t& r1, uint32_t& r2,
                                         uint32_t& r3, uint32_t addr) {
    asm volatile("ldmatrix.sync.aligned.m8n8.x4.trans.shared.b16 {%0,%1,%2,%3}, [%4];"
                 : "=r"(r0), "=r"(r1), "=r"(r2), "=r"(r3) : "r"(addr));
}
__device__ __forceinline__ void mma_bf16(float* c, const uint32_t* a, const uint32_t* b) {
    asm volatile(
        "mma.sync.aligned.m16n8k16.row.col.f32.bf16.bf16.f32 "
        "{%0,%1,%2,%3}, {%4,%5,%6,%7}, {%8,%9}, {%0,%1,%2,%3};"
        : "+f"(c[0]), "+f"(c[1]), "+f"(c[2]), "+f"(c[3])
        : "r"(a[0]), "r"(a[1]), "r"(a[2]), "r"(a[3]), "r"(b[0]), "r"(b[1]));
}
__device__ __forceinline__ void cp16(uint32_t dst, const void* src, bool pred) {
    int sz = pred ? 16 : 0;
    asm volatile("cp.async.cg.shared.global [%0], [%1], 16, %2;"
                 :: "r"(dst), "l"(src), "r"(sz) : "memory");
}
#define CP_COMMIT() asm volatile("cp.async.commit_group;" ::: "memory")
__device__ __forceinline__ uint32_t pack_hi(float x, float y) {
    __nv_bfloat16 hx = __float2bfloat16(x), hy = __float2bfloat16(y);
    return ((uint32_t)__bfloat16_as_ushort(hy) << 16) | __bfloat16_as_ushort(hx);
}

// ============================================================
// Streaming weight conversion: fp32 -> bf16 hi/lo, layout preserved.
// ============================================================
__global__ void convert_split_kernel(const float4* __restrict__ src,
                                     uint2* __restrict__ dh,
                                     uint2* __restrict__ dl, int n4) {
    int i = blockIdx.x * blockDim.x + threadIdx.x;
    if (i >= n4) return;
    float4 v = src[i];
    __nv_bfloat16 h0 = __float2bfloat16(v.x), h1 = __float2bfloat16(v.y);
    __nv_bfloat16 h2 = __float2bfloat16(v.z), h3 = __float2bfloat16(v.w);
    uint2 hh, ll;
    hh.x = ((uint32_t)__bfloat16_as_ushort(h1) << 16) | __bfloat16_as_ushort(h0);
    hh.y = ((uint32_t)__bfloat16_as_ushort(h3) << 16) | __bfloat16_as_ushort(h2);
    __nv_bfloat16 l0 = __float2bfloat16(v.x - __bfloat162float(h0));
    __nv_bfloat16 l1 = __float2bfloat16(v.y - __bfloat162float(h1));
    __nv_bfloat16 l2 = __float2bfloat16(v.z - __bfloat162float(h2));
    __nv_bfloat16 l3 = __float2bfloat16(v.w - __bfloat162float(h3));
    ll.x = ((uint32_t)__bfloat16_as_ushort(l1) << 16) | __bfloat16_as_ushort(l0);
    ll.y = ((uint32_t)__bfloat16_as_ushort(l3) << 16) | __bfloat16_as_ushort(l2);
    dh[i] = hh;
    dl[i] = ll;
}

// ============================================================
// HMMA GEMM, 64x64 C tile, K=1024 (16 blocks of 64), split-bf16 (3 MMA),
// B in native [k][n] layout (ldmatrix.trans), 3-stage cp.async, 2 CTAs/SM.
// MODE: 0=QKV, 1=OPROJ(+resid), 2=GATEUP(gather+swiglu->act), 3=DOWN(->eo)
// ============================================================
template <int MODE, int NN>
__global__ __launch_bounds__(256, 2) void mma_gemm(
    const __nv_bfloat16* __restrict__ Ah, const __nv_bfloat16* __restrict__ Al,
    const __nv_bfloat16* __restrict__ Bh, const __nv_bfloat16* __restrict__ Bl,
    const float* __restrict__ bias, const float* __restrict__ resid,
    float* __restrict__ Cout) {
    extern __shared__ __align__(1024) char dsm[];
    __shared__ int s_tok[64];

    const int tid = threadIdx.x, wid = tid >> 5, lane = tid & 31;
    const int wm = wid & 1, wn = wid >> 1;
    const int e = blockIdx.z;
    const int row0 = blockIdx.y * 64, col0 = blockIdx.x * 64;
    int cnt = Tc, off = 0;
    if (MODE >= 2) {
        cnt = g_cnt[e];
        off = g_off[e];
        if (row0 >= cnt) return;
    }
    const __nv_bfloat16* Bhg = Bh + (MODE >= 2 ? (size_t)e * 1024 * NN : 0);
    const __nv_bfloat16* Blg = Bl + (MODE >= 2 ? (size_t)e * 1024 * NN : 0);

    uint32_t base = (smem_to_u32(dsm) + 1023) & ~1023u;

    if (MODE == 2 && tid < 64) {
        int r = row0 + tid;
        s_tok[tid] = (r < cnt) ? g_tok[off + r] : -1;
    }
    if (MODE == 2) __syncthreads();

    // ---- issue one K-block stage: A[64m][64k], B[64k][64n], hi+lo ----
    auto issue_stage = [&](int kb, uint32_t buf) {
        const int kbase = kb * 64;
#pragma unroll
        for (int i = 0; i < 2; i++) {
            int c = tid + 256 * i;
            int row = c >> 3, k8 = c & 7;
            uint32_t raw = row * 128 + k8 * 16;
            uint32_t sw = raw ^ ((raw >> 3) & 0x70);
            size_t o;
            bool pred = true;
            if (MODE == 2) {
                int tok = s_tok[row];
                pred = tok >= 0;
                o = (size_t)(pred ? tok : 0) * 1024 + kbase + k8 * 8;
            } else if (MODE == 3) {
                int r = row0 + row;
                pred = r < cnt;
                o = (size_t)(off + (pred ? r : 0)) * 1024 + kbase + k8 * 8;
            } else {
                o = (size_t)(row0 + row) * 1024 + kbase + k8 * 8;
            }
            cp16(buf + sw, Ah + o, pred);
            cp16(buf + ASZ + sw, Al + o, pred);
        }
        // B: row = k (0..63), 16B chunk = 8 n-values
#pragma unroll
        for (int i = 0; i < 2; i++) {
            int c = tid + 256 * i;
            int row = c >> 3, k8 = c & 7;
            uint32_t raw = row * 128 + k8 * 16;
            uint32_t sw = raw ^ ((raw >> 3) & 0x70);
            size_t o = (size_t)(kbase + row) * NN + col0 + k8 * 8;
            cp16(buf + 2 * ASZ + sw, Bhg + o, true);
            cp16(buf + 2 * ASZ + BSZ + sw, Blg + o, true);
        }
        CP_COMMIT();
    };

    float acc[2][2][4] = {};

    const uint32_t a_raw0 = (uint32_t)(wm * 32 + (lane & 15)) * 128 + (lane >> 4) * 16;
    // trans-B lane base: matrix id = lane>>3; row = (m&1)*8 + lane&7; col8 = m>>1
    const int bm = lane >> 3;
    const uint32_t b_raw0 = (uint32_t)((bm & 1) * 8 + (lane & 7)) * 128 +
                            (uint32_t)(wn * 16 + (bm >> 1) * 8) * 2;

    auto compute = [&](uint32_t buf) {
        uint32_t AH = buf, AL = buf + ASZ, BH = buf + 2 * ASZ, BL = BH + BSZ;
#pragma unroll
        for (int ks = 0; ks < 4; ks++) {
            uint32_t ah[2][4], al[2][4], bh[2][2], bl[2][2];
#pragma unroll
            for (int mi = 0; mi < 2; mi++) {
                uint32_t raw = a_raw0 + mi * 2048 + ks * 32;
                uint32_t sw = raw ^ ((raw >> 3) & 0x70);
                ldm_x4(ah[mi][0], ah[mi][1], ah[mi][2], ah[mi][3], AH + sw);
                ldm_x4(al[mi][0], al[mi][1], al[mi][2], al[mi][3], AL + sw);
            }
            {
                uint32_t raw = b_raw0 + ks * 2048;   // +16 k-rows per step
                uint32_t sw = raw ^ ((raw >> 3) & 0x70);
                ldm_x4_t(bh[0][0], bh[0][1], bh[1][0], bh[1][1], BH + sw);
                ldm_x4_t(bl[0][0], bl[0][1], bl[1][0], bl[1][1], BL + sw);
            }
#pragma unroll
            for (int mi = 0; mi < 2; mi++)
#pragma unroll
                for (int ni = 0; ni < 2; ni++) {
                    mma_bf16(acc[mi][ni], ah[mi], bh[ni]);
                    mma_bf16(acc[mi][ni], ah[mi], bl[ni]);
                    mma_bf16(acc[mi][ni], al[mi], bh[ni]);
                }
        }
    };

    issue_stage(0, base);
    issue_stage(1, base + STAGE);
    issue_stage(2, base + 2 * STAGE);
    for (int kb = 0; kb < 16; kb++) {
        if (kb < 14)
            asm volatile("cp.async.wait_group 2;" ::: "memory");
        else if (kb == 14)
            asm volatile("cp.async.wait_group 1;" ::: "memory");
        else
            asm volatile("cp.async.wait_group 0;" ::: "memory");
        __syncthreads();
        uint32_t buf = base + (uint32_t)(kb % 3) * STAGE;
        compute(buf);
        __syncthreads();
        if (kb + 3 < 16) issue_stage(kb + 3, buf);
    }

    // ---- epilogue ----
    const int g = lane >> 2, tg = lane & 3;
#pragma unroll
    for (int mi = 0; mi < 2; mi++) {
#pragma unroll
        for (int ni = 0; ni < 2; ni++) {
#pragma unroll
            for (int hh = 0; hh < 2; hh++) {
                int r = row0 + wm * 32 + mi * 16 + g + hh * 8;
                int c = col0 + wn * 16 + ni * 8 + tg * 2;
                float v0 = acc[mi][ni][2 * hh + 0];
                float v1 = acc[mi][ni][2 * hh + 1];
                if (MODE == 0) {
                    size_t p = (size_t)r * NN + c;
                    Cout[p] = v0 + bias[c];
                    Cout[p + 1] = v1 + bias[c + 1];
                } else if (MODE == 1) {
                    size_t p = (size_t)r * NN + c;
                    Cout[p] = v0 + bias[c] + resid[p];
                    Cout[p + 1] = v1 + bias[c + 1] + resid[p + 1];
                } else if (MODE == 2) {
                    if (r < cnt) {
                        const float* bg = bias + (size_t)e * 2 * FFNc;
                        float gv = v0 + bg[c];
                        float uv = v1 + bg[c + 1];
                        gv = fminf(gv, LIMITc);
                        uv = fminf(fmaxf(uv, -LIMITc), LIMITc);
                        float glu = gv / (1.0f + expf(-ALPHAc * gv));
                        float a = (uv + 1.0f) * glu;
                        __nv_bfloat16 h = __float2bfloat16(a);
                        __nv_bfloat16 l = __float2bfloat16(a - __bfloat162float(h));
                        size_t p = (size_t)(off + r) * FFNc + (c >> 1);
                        g_act_hi[p] = h;
                        g_act_lo[p] = l;
                    }
                } else {
                    if (r < cnt) {
                        const float* bd = bias + (size_t)e * Hc;
                        size_t p = (size_t)(off + r) * Hc + c;
                        g_eo[p] = v0 + bd[c];
                        g_eo[p + 1] = v1 + bd[c + 1];
                    }
                }
            }
        }
    }
}

// ============================================================
// RMSNorm (ln1) -> bf16 hi/lo split
// ============================================================
__global__ void rmsnorm1_kernel(const float* __restrict__ x,
                                const float* __restrict__ w) {
    int t = blockIdx.x, tid = threadIdx.x;
    const float* xr = x + (size_t)t * Hc;
    float ss = 0.f;
#pragma unroll
    for (int i = 0; i < 4; i++) { float v = xr[tid + 256 * i]; ss += v * v; }
#pragma unroll
    for (int o = 16; o; o >>= 1) ss += __shfl_xor_sync(~0u, ss, o);
    __shared__ float red[8];
    if ((tid & 31) == 0) red[tid >> 5] = ss;
    __syncthreads();
    float tot = 0.f;
#pragma unroll
    for (int i = 0; i < 8; i++) tot += red[i];
    float rinv = rsqrtf(tot * (1.0f / Hc) + EPSc);
#pragma unroll
    for (int i = 0; i < 4; i++) {
        int c = tid + 256 * i;
        float v = xr[c] * w[c] * rinv;
        __nv_bfloat16 h = __float2bfloat16(v);
        g_xnh[(size_t)t * Hc + c] = h;
        g_xnl[(size_t)t * Hc + c] = __float2bfloat16(v - __bfloat162float(h));
    }
}

// ============================================================
// Tiled windowed GQA attention with sink.
// Grid (qt=8, kvh=4, b=4), 256 threads. 16 queries x 4 heads per CTA,
// shared 143-key K/V window in smem.
// ============================================================
__global__ __launch_bounds__(256, 1) void attn_kernel(
    const float* __restrict__ qkvb, const float* __restrict__ kvc,
    const int* __restrict__ pidx, const float* __restrict__ sinks) {
    extern __shared__ float sm[];
    float* Ks = sm;                       // [144][68] (143 rows used)
    float* Vs = Ks + AT_KV;               // [144][68]
    float* Qs = Vs + AT_KV;               // [4][16][64], pre-scaled
    float* Ss = Qs + AT_Q;                // [16][128][4]
    float* Rd = Ss + AT_S;                // [16][4]

    const int qt = blockIdx.x, kvh = blockIdx.y, b = blockIdx.z;
    const int q0 = qt * 16;
    const int tid = threadIdx.x;

    // ---- load K/V window: keys kpos = 769+q0+kk, kk = 0..142 ----
    for (int i = tid; i < 143 * 16; i += 256) {
        int kk = i >> 4, d = (i & 15) * 4;
        int kpos = 769 + q0 + kk;
        const float *kp, *vp;
        if (kpos >= Sq - Qc) {
            int tt = b * Qc + (kpos - (Sq - Qc));
            kp = qkvb + (size_t)tt * QKVW + (NQc + kvh) * HDc + d;
            vp = qkvb + (size_t)tt * QKVW + (NQc + NKVc + kvh) * HDc + d;
        } else {
            int pg = pidx[b * Pc + (kpos >> 7)];
            size_t bb = ((size_t)(pg * 2) * PSc + (kpos & 127)) * (NKVc * HDc) + kvh * HDc + d;
            kp = kvc + bb;
            vp = kvc + bb + (size_t)PSc * NKVc * HDc;
        }
        *(float4*)(Ks + kk * 68 + d) = *(const float4*)kp;
        *(float4*)(Vs + kk * 68 + d) = *(const float4*)vp;
    }
    // ---- load Q (scaled) ----
    for (int i = tid; i < 1024; i += 256) {
        int h = i >> 8, qq = (i >> 4) & 15, d = (i & 15) * 4;
        int t = b * Qc + q0 + qq;
        float4 v = *(const float4*)(qkvb + (size_t)t * QKVW + (kvh * 4 + h) * HDc + d);
        v.x *= SCALEc; v.y *= SCALEc; v.z *= SCALEc; v.w *= SCALEc;
        *(float4*)(Qs + (h * 16 + qq) * 64 + d) = v;
    }
    __syncthreads();

    // ---- scores: thread (qq = tid>>4, lane = tid&15); keys l = lane+16j ----
    {
        const int qq = tid >> 4, lane = tid & 15;
        float acc[8][4];
#pragma unroll
        for (int j = 0; j < 8; j++)
#pragma unroll
            for (int h = 0; h < 4; h++) acc[j][h] = 0.f;
#pragma unroll
        for (int dc = 0; dc < 4; dc++) {
            float4 qr[4][4];
#pragma unroll
            for (int h = 0; h < 4; h++)
#pragma unroll
                for (int dd = 0; dd < 4; dd++)
                    qr[h][dd] = *(float4*)(Qs + (h * 16 + qq) * 64 + dc * 16 + dd * 4);
#pragma unroll
            for (int j = 0; j < 8; j++) {
                int kk = qq + lane + 16 * j;
                const float* kr = Ks + kk * 68 + dc * 16;
#pragma unroll
                for (int dd = 0; dd < 4; dd++) {
                    float4 k4 = *(const float4*)(kr + dd * 4);
#pragma unroll
                    for (int h = 0; h < 4; h++)
                        acc[j][h] += qr[h][dd].x * k4.x + qr[h][dd].y * k4.y +
                                     qr[h][dd].z * k4.z + qr[h][dd].w * k4.w;
                }
            }
        }
#pragma unroll
        for (int j = 0; j < 8; j++) {
            int l = lane + 16 * j;
#pragma unroll
            for (int h = 0; h < 4; h++) Ss[(qq * 128 + l) * 4 + h] = acc[j][h];
        }
    }
    __syncthreads();

    // ---- softmax per (qq,h) row; 4 lanes per row ----
    {
        const int row = tid >> 2, l2 = tid & 3;
        const int sq = row >> 2, sh = row & 3;
        float m = -1e30f;
        for (int k = l2; k < 128; k += 4) m = fmaxf(m, Ss[(sq * 128 + k) * 4 + sh]);
        m = fmaxf(m, __shfl_xor_sync(~0u, m, 1));
        m = fmaxf(m, __shfl_xor_sync(~0u, m, 2));
        float sum = 0.f;
        for (int k = l2; k < 128; k += 4) {
            float p = expf(Ss[(sq * 128 + k) * 4 + sh] - m);
            Ss[(sq * 128 + k) * 4 + sh] = p;
            sum += p;
        }
        sum += __shfl_xor_sync(~0u, sum, 1);
        sum += __shfl_xor_sync(~0u, sum, 2);
        if (l2 == 0) Rd[sq * 4 + sh] = 1.0f / (sum + expf(sinks[kvh * 4 + sh] - m));
    }
    __syncthreads();

    // ---- output: thread (qq, lane) owns dims d = lane*4..+3 for 4 heads ----
    {
        const int qq = tid >> 4, lane = tid & 15;
        const int d = lane * 4;
        float4 oa[4];
#pragma unroll
        for (int h = 0; h < 4; h++) oa[h] = make_float4(0.f, 0.f, 0.f, 0.f);
        for (int l = 0; l < 128; l++) {
            float4 v = *(const float4*)(Vs + (qq + l) * 68 + d);
            const float* pr = Ss + (qq * 128 + l) * 4;
#pragma unroll
            for (int h = 0; h < 4; h++) {
                float p = pr[h];
                oa[h].x += p * v.x; oa[h].y += p * v.y;
                oa[h].z += p * v.z; oa[h].w += p * v.w;
            }
        }
        int t = b * Qc + q0 + qq;
#pragma unroll
        for (int h = 0; h < 4; h++) {
            float r = Rd[qq * 4 + h];
            float x0 = oa[h].x * r, x1 = oa[h].y * r, x2 = oa[h].z * r, x3 = oa[h].w * r;
            size_t p2 = (size_t)t * Hc + (kvh * 4 + h) * HDc + d;
            uint2 hh, ll;
            __nv_bfloat16 b0 = __float2bfloat16(x0), b1 = __float2bfloat16(x1);
            __nv_bfloat16 b2 = __float2bfloat16(x2), b3 = __float2bfloat16(x3);
            hh.x = ((uint32_t)__bfloat16_as_ushort(b1) << 16) | __bfloat16_as_ushort(b0);
            hh.y = ((uint32_t)__bfloat16_as_ushort(b3) << 16) | __bfloat16_as_ushort(b2);
            __nv_bfloat16 c0 = __float2bfloat16(x0 - __bfloat162float(b0));
            __nv_bfloat16 c1 = __float2bfloat16(x1 - __bfloat162float(b1));
            __nv_bfloat16 c2 = __float2bfloat16(x2 - __bfloat162float(b2));
            __nv_bfloat16 c3 = __float2bfloat16(x3 - __bfloat162float(b3));
            ll.x = ((uint32_t)__bfloat16_as_ushort(c1) << 16) | __bfloat16_as_ushort(c0);
            ll.y = ((uint32_t)__bfloat16_as_ushort(c3) << 16) | __bfloat16_as_ushort(c2);
            *(uint2*)(g_ath + p2) = hh;
            *(uint2*)(g_atl + p2) = ll;
        }
    }
}

// ============================================================
// Router: rmsnorm(ln2) -> x2 (bf16 split), logits, top-2 weights
// ============================================================
__global__ void router_kernel(const float* __restrict__ ln2,
                              const float* __restrict__ Wr,
                              const float* __restrict__ br) {
    int t = blockIdx.x, tid = threadIdx.x;
    __shared__ float sx[Hc];
    __shared__ float red[8];
    __shared__ float lg[Ec];
    const float* hr = g_h + (size_t)t * Hc;
    float ss = 0.f;
#pragma unroll
    for (int i = 0; i < 4; i++) { float v = hr[tid + 256 * i]; ss += v * v; }
#pragma unroll
    for (int o = 16; o; o >>= 1) ss += __shfl_xor_sync(~0u, ss, o);
    if ((tid & 31) == 0) red[tid >> 5] = ss;
    __syncthreads();
    float tot = 0.f;
#pragma unroll
    for (int i = 0; i < 8; i++) tot += red[i];
    float rinv = rsqrtf(tot * (1.0f / Hc) + EPSc);
#pragma unroll
    for (int i = 0; i < 4; i++) {
        int c = tid + 256 * i;
        float v = hr[c] * ln2[c] * rinv;
        sx[c] = v;
        __nv_bfloat16 hb = __float2bfloat16(v);
        g_x2h[(size_t)t * Hc + c] = hb;
        g_x2l[(size_t)t * Hc + c] = __float2bfloat16(v - __bfloat162float(hb));
    }
    __syncthreads();
    int w = tid >> 5, lane = tid & 31;
    float s = 0.f;
    for (int c = lane; c < Hc; c += 32) s += sx[c] * Wr[c * Ec + w];
#pragma unroll
    for (int o = 16; o; o >>= 1) s += __shfl_xor_sync(~0u, s, o);
    if (lane == 0) lg[w] = s + br[w];
    __syncthreads();
    if (tid == 0) {
        int i0 = 0; float v0 = lg[0];
#pragma unroll
        for (int e = 1; e < Ec; e++) if (lg[e] > v0) { v0 = lg[e]; i0 = e; }
        int i1 = -1; float v1 = -1e30f;
#pragma unroll
        for (int e = 0; e < Ec; e++) {
            if (e == i0) continue;
            if (lg[e] > v1) { v1 = lg[e]; i1 = e; }
        }
        float e1 = expf(v1 - v0);
        g_eidx[t * 2] = i0; g_eidx[t * 2 + 1] = i1;
        g_ewt[t * 2] = 1.0f / (1.0f + e1);
        g_ewt[t * 2 + 1] = e1 / (1.0f + e1);
    }
}

// ============================================================
// Bucket tokens by expert (single block)
// ============================================================
__global__ void bucket_kernel() {
    __shared__ int c1[Ec], c2[Ec], so[Ec];
    int tid = threadIdx.x;
    if (tid < Ec) { c1[tid] = 0; c2[tid] = 0; }
    __syncthreads();
    for (int i = tid; i < Tc * 2; i += blockDim.x) atomicAdd(&c1[g_eidx[i]], 1);
    __syncthreads();
    if (tid == 0) {
        int run = 0;
        for (int e = 0; e < Ec; e++) { so[e] = run; run += c1[e]; }
    }
    __syncthreads();
    if (tid < Ec) { g_cnt[tid] = c1[tid]; g_off[tid] = so[tid]; }
    for (int i = tid; i < Tc * 2; i += blockDim.x) {
        int e = g_eidx[i];
        int r = atomicAdd(&c2[e], 1);
        int slot = so[e] + r;
        g_tok[slot] = i >> 1;
        g_slotof[i] = slot;
    }
}

// ============================================================
// Final combine
// ============================================================
__global__ void combine_kernel(float* __restrict__ out) {
    int t = blockIdx.x, tid = threadIdx.x;
    float w0 = g_ewt[t * 2], w1 = g_ewt[t * 2 + 1];
    int s0 = g_slotof[t * 2], s1 = g_slotof[t * 2 + 1];
#pragma unroll
    for (int i = 0; i < 4; i++) {
        int c = tid + 256 * i;
        out[(size_t)t * Hc + c] = g_h[(size_t)t * Hc + c]
                                + w0 * g_eo[(size_t)s0 * Hc + c]
                                + w1 * g_eo[(size_t)s1 * Hc + c];
    }
}

// ============================================================
extern "C" void kernel_launch(void* const* d_in, const int* in_sizes, int n_in,
                              void* d_out, int out_size) {
    const float* hidden = (const float*)d_in[0];
    const float* kvc    = (const float*)d_in[1];
    const int*   pidx   = (const int*)d_in[3];
    const float* sinks  = (const float*)d_in[4];
    const float* w_qkv  = (const float*)d_in[5];
    const float* b_qkv  = (const float*)d_in[6];
    const float* w_o    = (const float*)d_in[7];
    const float* b_o    = (const float*)d_in[8];
    const float* ln1    = (const float*)d_in[9];
    const float* ln2    = (const float*)d_in[10];
    const float* w_r    = (const float*)d_in[11];
    const float* b_r    = (const float*)d_in[12];
    const float* w_gu   = (const float*)d_in[13];
    const float* b_gu   = (const float*)d_in[14];
    const float* w_d    = (const float*)d_in[15];
    const float* b_d    = (const float*)d_in[16];
    float* out = (float*)d_out;

    void *pq, *ph;
    void *pxh, *pxl, *pah, *pal, *px2h, *px2l, *pacth, *pactl;
    void *pwqh, *pwql, *pwoh, *pwol, *pwguh, *pwgul, *pwdh, *pwdl;
    cudaGetSymbolAddress(&pq, g_qkv);
    cudaGetSymbolAddress(&ph, g_h);
    cudaGetSymbolAddress(&pxh, g_xnh);  cudaGetSymbolAddress(&pxl, g_xnl);
    cudaGetSymbolAddress(&pah, g_ath);  cudaGetSymbolAddress(&pal, g_atl);
    cudaGetSymbolAddress(&px2h, g_x2h); cudaGetSymbolAddress(&px2l, g_x2l);
    cudaGetSymbolAddress(&pacth, g_act_hi); cudaGetSymbolAddress(&pactl, g_act_lo);
    cudaGetSymbolAddress(&pwqh, g_wqh); cudaGetSymbolAddress(&pwql, g_wql);
    cudaGetSymbolAddress(&pwoh, g_woh); cudaGetSymbolAddress(&pwol, g_wol);
    cudaGetSymbolAddress(&pwguh, g_wguh); cudaGetSymbolAddress(&pwgul, g_wgul);
    cudaGetSymbolAddress(&pwdh, g_wdh);   cudaGetSymbolAddress(&pwdl, g_wdl);

    cudaFuncSetAttribute(mma_gemm<0, QKVW>, cudaFuncAttributeMaxDynamicSharedMemorySize, GEMM_SMEM);
    cudaFuncSetAttribute(mma_gemm<1, Hc>, cudaFuncAttributeMaxDynamicSharedMemorySize, GEMM_SMEM);
    cudaFuncSetAttribute(mma_gemm<2, 2 * FFNc>, cudaFuncAttributeMaxDynamicSharedMemorySize, GEMM_SMEM);
    cudaFuncSetAttribute(mma_gemm<3, Hc>, cudaFuncAttributeMaxDynamicSharedMemorySize, GEMM_SMEM);
    cudaFuncSetAttribute(attn_kernel, cudaFuncAttributeMaxDynamicSharedMemorySize, ATT_SMEM);

    // 0) weight prep: streaming bf16 hi/lo split (layout preserved)
    {
        int n4;
        n4 = Hc * QKVW / 4;
        convert_split_kernel<<<(n4 + 255) / 256, 256>>>(
            (const float4*)w_qkv, (uint2*)pwqh, (uint2*)pwql, n4);
        n4 = Hc * Hc / 4;
        convert_split_kernel<<<(n4 + 255) / 256, 256>>>(
            (const float4*)w_o, (uint2*)pwoh, (uint2*)pwol, n4);
        n4 = Ec * Hc * 2 * FFNc / 4;
        convert_split_kernel<<<(n4 + 255) / 256, 256>>>(
            (const float4*)w_gu, (uint2*)pwguh, (uint2*)pwgul, n4);
        n4 = Ec * FFNc * Hc / 4;
        convert_split_kernel<<<(n4 + 255) / 256, 256>>>(
            (const float4*)w_d, (uint2*)pwdh, (uint2*)pwdl, n4);
    }

    // 1) ln1 -> split
    rmsnorm1_kernel<<<Tc, 256>>>(hidden, ln1);
    // 2) QKV GEMM
    mma_gemm<0, QKVW><<<dim3(QKVW / 64, Tc / 64, 1), 256, GEMM_SMEM>>>(
        (const __nv_bfloat16*)pxh, (const __nv_bfloat16*)pxl,
        (const __nv_bfloat16*)pwqh, (const __nv_bfloat16*)pwql,
        b_qkv, nullptr, (float*)pq);
    // 3) attention (tiled)
    attn_kernel<<<dim3(8, NKVc, Bc), 256, ATT_SMEM>>>(
        (const float*)pq, kvc, pidx, sinks);
    // 4) O proj + residual
    mma_gemm<1, Hc><<<dim3(Hc / 64, Tc / 64, 1), 256, GEMM_SMEM>>>(
        (const __nv_bfloat16*)pah, (const __nv_bfloat16*)pal,
        (const __nv_bfloat16*)pwoh, (const __nv_bfloat16*)pwol,
        b_o, hidden, (float*)ph);
    // 5) router
    router_kernel<<<Tc, 256>>>(ln2, w_r, b_r);
    // 6) bucket
    bucket_kernel<<<1, 256>>>();
    // 7) gate_up + swiglu -> act split
    mma_gemm<2, 2 * FFNc><<<dim3(2 * FFNc / 64, 16, Ec), 256, GEMM_SMEM>>>(
        (const __nv_bfloat16*)px2h, (const __nv_bfloat16*)px2l,
        (const __nv_bfloat16*)pwguh, (const __nv_bfloat16*)pwgul,
        b_gu, nullptr, nullptr);
    // 8) down -> g_eo
    mma_gemm<3, Hc><<<dim3(Hc / 64, 16, Ec), 256, GEMM_SMEM>>>(
        (const __nv_bfloat16*)pacth, (const __nv_bfloat16*)pactl,
        (const __nv_bfloat16*)pwdh, (const __nv_bfloat16*)pwdl,
        b_d, nullptr, nullptr);
    // 9) combine
    combine_kernel<<<Tc, 256>>>(out);
}

// round 7
// speedup vs baseline: 4.3186x; 1.0764x over previous
#include <cuda_runtime.h>
#include <cuda_bf16.h>
#include <math.h>
#include <stdint.h>

// ---- static problem config ----
namespace {
constexpr int Hc = 1024, HDc = 64, NQc = 16, NKVc = 4, Ec = 8, FFNc = 1024;
constexpr int Bc = 4, Qc = 128, Pc = 8, PSc = 128, Sq = 1024, Tc = 512;
constexpr int QKVW = HDc * (NQc + 2 * NKVc);   // 1536
constexpr float SCALEc = 0.125f;
constexpr float ALPHAc = 1.702f, LIMITc = 7.0f, EPSc = 1e-5f;
constexpr int SLOTS = 1536;                    // padded slot capacity (1024 + 8*64)
constexpr int MAXTILES = 24;
// GEMM smem: 3 stages x (AH 8K | AL 8K | BH 8K | BL 8K) = 96KB -> 2 CTAs/SM
constexpr uint32_t ASZ = 64 * 64 * 2;
constexpr uint32_t BSZ = 64 * 64 * 2;
constexpr uint32_t STAGE = 2 * ASZ + 2 * BSZ;  // 32768
constexpr int NSTAGE = 3;
constexpr int GEMM_SMEM = NSTAGE * (int)STAGE + 1024;
// attention smem (floats)
constexpr int AT_KV = 144 * 68;
constexpr int AT_Q = 4 * 16 * 64;
constexpr int AT_S = 16 * 128 * 4;
constexpr int ATT_SMEM = (2 * AT_KV + AT_Q + AT_S + 64) * 4;
}

// ---- scratch (static __device__, allocation-free) ----
__device__ float g_qkv[Tc * QKVW];
__device__ float g_h[Tc * Hc];
__device__ __nv_bfloat16 g_xnh[Tc * Hc], g_xnl[Tc * Hc];
__device__ __nv_bfloat16 g_ath[Tc * Hc], g_atl[Tc * Hc];
__device__ __nv_bfloat16 g_x2h[Tc * Hc], g_x2l[Tc * Hc];
__device__ __nv_bfloat16 g_act_hi[SLOTS * FFNc], g_act_lo[SLOTS * FFNc];
__device__ float g_eo[SLOTS * Hc];
__device__ int   g_eidx[Tc * 2];
__device__ float g_ewt[Tc * 2];
__device__ int   g_cnt[Ec];
__device__ int   g_poff[Ec];        // padded (64-aligned) start of expert region
__device__ int   g_tok[SLOTS];      // -1 = ghost slot
__device__ int   g_slotof[Tc * 2];
__device__ int   g_tile_e[MAXTILES];
__device__ int   g_ntiles;
// split weights, native [K][N] layout, bf16 hi/lo
__device__ __nv_bfloat16 g_wqh[Hc * QKVW], g_wql[Hc * QKVW];
__device__ __nv_bfloat16 g_woh[Hc * Hc], g_wol[Hc * Hc];
__device__ __nv_bfloat16 g_wguh[Ec * Hc * 2 * FFNc], g_wgul[Ec * Hc * 2 * FFNc];
__device__ __nv_bfloat16 g_wdh[Ec * FFNc * Hc], g_wdl[Ec * FFNc * Hc];

// ============================================================
__device__ __forceinline__ uint32_t smem_to_u32(const void* p) {
    uint32_t a;
    asm("{ .reg .u64 t; cvta.to.shared.u64 t, %1; cvt.u32.u64 %0, t; }" : "=r"(a) : "l"(p));
    return a;
}
__device__ __forceinline__ void ldm_x4(uint32_t& r0, uint32_t& r1, uint32_t& r2,
                                       uint32_t& r3, uint32_t addr) {
    asm volatile("ldmatrix.sync.aligned.m8n8.x4.shared.b16 {%0,%1,%2,%3}, [%4];"
                 : "=r"(r0), "=r"(r1), "=r"(r2), "=r"(r3) : "r"(addr));
}
__device__ __forceinline__ void ldm_x4_t(uint32_t& r0, uint32_t& r1, uint32_t& r2,
                                         uint32_t& r3, uint32_t addr) {
    asm volatile("ldmatrix.sync.aligned.m8n8.x4.trans.shared.b16 {%0,%1,%2,%3}, [%4];"
                 : "=r"(r0), "=r"(r1), "=r"(r2), "=r"(r3) : "r"(addr));
}
__device__ __forceinline__ void mma_bf16(float* c, const uint32_t* a, const uint32_t* b) {
    asm volatile(
        "mma.sync.aligned.m16n8k16.row.col.f32.bf16.bf16.f32 "
        "{%0,%1,%2,%3}, {%4,%5,%6,%7}, {%8,%9}, {%0,%1,%2,%3};"
        : "+f"(c[0]), "+f"(c[1]), "+f"(c[2]), "+f"(c[3])
        : "r"(a[0]), "r"(a[1]), "r"(a[2]), "r"(a[3]), "r"(b[0]), "r"(b[1]));
}
__device__ __forceinline__ void cp16(uint32_t dst, const void* src, bool pred) {
    int sz = pred ? 16 : 0;
    asm volatile("cp.async.cg.shared.global [%0], [%1], 16, %2;"
                 :: "r"(dst), "l"(src), "r"(sz) : "memory");
}
#define CP_COMMIT() asm volatile("cp.async.commit_group;" ::: "memory")

// ============================================================
// Streaming weight conversion: fp32 -> bf16 hi/lo, layout preserved.
// ============================================================
__global__ void convert_split_kernel(const float4* __restrict__ src,
                                     uint2* __restrict__ dh,
                                     uint2* __restrict__ dl, int n4) {
    int i = blockIdx.x * blockDim.x + threadIdx.x;
    if (i >= n4) return;
    float4 v = src[i];
    __nv_bfloat16 h0 = __float2bfloat16(v.x), h1 = __float2bfloat16(v.y);
    __nv_bfloat16 h2 = __float2bfloat16(v.z), h3 = __float2bfloat16(v.w);
    uint2 hh, ll;
    hh.x = ((uint32_t)__bfloat16_as_ushort(h1) << 16) | __bfloat16_as_ushort(h0);
    hh.y = ((uint32_t)__bfloat16_as_ushort(h3) << 16) | __bfloat16_as_ushort(h2);
    __nv_bfloat16 l0 = __float2bfloat16(v.x - __bfloat162float(h0));
    __nv_bfloat16 l1 = __float2bfloat16(v.y - __bfloat162float(h1));
    __nv_bfloat16 l2 = __float2bfloat16(v.z - __bfloat162float(h2));
    __nv_bfloat16 l3 = __float2bfloat16(v.w - __bfloat162float(h3));
    ll.x = ((uint32_t)__bfloat16_as_ushort(l1) << 16) | __bfloat16_as_ushort(l0);
    ll.y = ((uint32_t)__bfloat16_as_ushort(l3) << 16) | __bfloat16_as_ushort(l2);
    dh[i] = hh;
    dl[i] = ll;
}

// ============================================================
// HMMA GEMM, 64x64 C tile, K=1024, split-bf16 (3 MMA), 3-stage cp.async.
// MODE: 0=QKV, 1=OPROJ(+resid), 2=GATEUP(gather+swiglu->act), 3=DOWN(->eo)
// MODE>=2: blockIdx.y = padded tile index; expert from g_tile_e.
// ============================================================
template <int MODE, int NN>
__global__ __launch_bounds__(256, 2) void mma_gemm(
    const __nv_bfloat16* __restrict__ Ah, const __nv_bfloat16* __restrict__ Al,
    const __nv_bfloat16* __restrict__ Bh, const __nv_bfloat16* __restrict__ Bl,
    const float* __restrict__ bias, const float* __restrict__ resid,
    float* __restrict__ Cout) {
    extern __shared__ __align__(1024) char dsm[];
    __shared__ int s_tok[64];

    const int tid = threadIdx.x, wid = tid >> 5, lane = tid & 31;
    const int wm = wid & 1, wn = wid >> 1;
    const int row0 = blockIdx.y * 64, col0 = blockIdx.x * 64;
    int e = 0, lb = 0, cnt = Tc;
    if (MODE >= 2) {
        if ((int)blockIdx.y >= g_ntiles) return;
        e = g_tile_e[blockIdx.y];
        lb = row0 - g_poff[e];
        cnt = g_cnt[e];
    }
    const __nv_bfloat16* Bhg = Bh + (MODE >= 2 ? (size_t)e * 1024 * NN : 0);
    const __nv_bfloat16* Blg = Bl + (MODE >= 2 ? (size_t)e * 1024 * NN : 0);

    uint32_t base = (smem_to_u32(dsm) + 1023) & ~1023u;

    if (MODE == 2 && tid < 64) s_tok[tid] = g_tok[row0 + tid];
    if (MODE == 2) __syncthreads();

    auto issue_stage = [&](int kb, uint32_t buf) {
        const int kbase = kb * 64;
#pragma unroll
        for (int i = 0; i < 2; i++) {
            int c = tid + 256 * i;
            int row = c >> 3, k8 = c & 7;
            uint32_t raw = row * 128 + k8 * 16;
            uint32_t sw = raw ^ ((raw >> 3) & 0x70);
            size_t o;
            bool pred = true;
            if (MODE == 2) {
                int tok = s_tok[row];
                pred = tok >= 0;
                o = (size_t)(pred ? tok : 0) * 1024 + kbase + k8 * 8;
            } else if (MODE == 3) {
                pred = (lb + row) < cnt;
                o = (size_t)(row0 + row) * 1024 + kbase + k8 * 8;
            } else {
                o = (size_t)(row0 + row) * 1024 + kbase + k8 * 8;
            }
            cp16(buf + sw, Ah + o, pred);
            cp16(buf + ASZ + sw, Al + o, pred);
        }
#pragma unroll
        for (int i = 0; i < 2; i++) {
            int c = tid + 256 * i;
            int row = c >> 3, k8 = c & 7;
            uint32_t raw = row * 128 + k8 * 16;
            uint32_t sw = raw ^ ((raw >> 3) & 0x70);
            size_t o = (size_t)(kbase + row) * NN + col0 + k8 * 8;
            cp16(buf + 2 * ASZ + sw, Bhg + o, true);
            cp16(buf + 2 * ASZ + BSZ + sw, Blg + o, true);
        }
        CP_COMMIT();
    };

    float acc[2][2][4] = {};

    const uint32_t a_raw0 = (uint32_t)(wm * 32 + (lane & 15)) * 128 + (lane >> 4) * 16;
    const int bm = lane >> 3;
    const uint32_t b_raw0 = (uint32_t)((bm & 1) * 8 + (lane & 7)) * 128 +
                            (uint32_t)(wn * 16 + (bm >> 1) * 8) * 2;

    auto compute = [&](uint32_t buf) {
        uint32_t AH = buf, AL = buf + ASZ, BH = buf + 2 * ASZ, BL = BH + BSZ;
#pragma unroll
        for (int ks = 0; ks < 4; ks++) {
            uint32_t ah[2][4], al[2][4], bh[2][2], bl[2][2];
#pragma unroll
            for (int mi = 0; mi < 2; mi++) {
                uint32_t raw = a_raw0 + mi * 2048 + ks * 32;
                uint32_t sw = raw ^ ((raw >> 3) & 0x70);
                ldm_x4(ah[mi][0], ah[mi][1], ah[mi][2], ah[mi][3], AH + sw);
                ldm_x4(al[mi][0], al[mi][1], al[mi][2], al[mi][3], AL + sw);
            }
            {
                uint32_t raw = b_raw0 + ks * 2048;
                uint32_t sw = raw ^ ((raw >> 3) & 0x70);
                ldm_x4_t(bh[0][0], bh[0][1], bh[1][0], bh[1][1], BH + sw);
                ldm_x4_t(bl[0][0], bl[0][1], bl[1][0], bl[1][1], BL + sw);
            }
#pragma unroll
            for (int mi = 0; mi < 2; mi++)
#pragma unroll
                for (int ni = 0; ni < 2; ni++) {
                    mma_bf16(acc[mi][ni], ah[mi], bh[ni]);
                    mma_bf16(acc[mi][ni], ah[mi], bl[ni]);
                    mma_bf16(acc[mi][ni], al[mi], bh[ni]);
                }
        }
    };

    issue_stage(0, base);
    issue_stage(1, base + STAGE);
    issue_stage(2, base + 2 * STAGE);
    for (int kb = 0; kb < 16; kb++) {
        if (kb < 14)
            asm volatile("cp.async.wait_group 2;" ::: "memory");
        else if (kb == 14)
            asm volatile("cp.async.wait_group 1;" ::: "memory");
        else
            asm volatile("cp.async.wait_group 0;" ::: "memory");
        __syncthreads();
        uint32_t buf = base + (uint32_t)(kb % 3) * STAGE;
        compute(buf);
        __syncthreads();
        if (kb + 3 < 16) issue_stage(kb + 3, buf);
    }

    // ---- epilogue ----
    const int g = lane >> 2, tg = lane & 3;
#pragma unroll
    for (int mi = 0; mi < 2; mi++) {
#pragma unroll
        for (int ni = 0; ni < 2; ni++) {
#pragma unroll
            for (int hh = 0; hh < 2; hh++) {
                int rt = wm * 32 + mi * 16 + g + hh * 8;   // 0..63 within tile
                int c = col0 + wn * 16 + ni * 8 + tg * 2;
                float v0 = acc[mi][ni][2 * hh + 0];
                float v1 = acc[mi][ni][2 * hh + 1];
                if (MODE == 0) {
                    size_t p = (size_t)(row0 + rt) * NN + c;
                    Cout[p] = v0 + bias[c];
                    Cout[p + 1] = v1 + bias[c + 1];
                } else if (MODE == 1) {
                    size_t p = (size_t)(row0 + rt) * NN + c;
                    Cout[p] = v0 + bias[c] + resid[p];
                    Cout[p + 1] = v1 + bias[c + 1] + resid[p + 1];
                } else if (MODE == 2) {
                    if (lb + rt < cnt) {
                        const float* bg = bias + (size_t)e * 2 * FFNc;
                        float gv = v0 + bg[c];
                        float uv = v1 + bg[c + 1];
                        gv = fminf(gv, LIMITc);
                        uv = fminf(fmaxf(uv, -LIMITc), LIMITc);
                        float glu = gv / (1.0f + expf(-ALPHAc * gv));
                        float a = (uv + 1.0f) * glu;
                        __nv_bfloat16 h = __float2bfloat16(a);
                        __nv_bfloat16 l = __float2bfloat16(a - __bfloat162float(h));
                        size_t p = (size_t)(row0 + rt) * FFNc + (c >> 1);
                        g_act_hi[p] = h;
                        g_act_lo[p] = l;
                    }
                } else {
                    if (lb + rt < cnt) {
                        const float* bd = bias + (size_t)e * Hc;
                        size_t p = (size_t)(row0 + rt) * Hc + c;
                        g_eo[p] = v0 + bd[c];
                        g_eo[p + 1] = v1 + bd[c + 1];
                    }
                }
            }
        }
    }
}

// ============================================================
// RMSNorm (ln1) -> bf16 hi/lo split
// ============================================================
__global__ void rmsnorm1_kernel(const float* __restrict__ x,
                                const float* __restrict__ w) {
    int t = blockIdx.x, tid = threadIdx.x;
    const float* xr = x + (size_t)t * Hc;
    float ss = 0.f;
#pragma unroll
    for (int i = 0; i < 4; i++) { float v = xr[tid + 256 * i]; ss += v * v; }
#pragma unroll
    for (int o = 16; o; o >>= 1) ss += __shfl_xor_sync(~0u, ss, o);
    __shared__ float red[8];
    if ((tid & 31) == 0) red[tid >> 5] = ss;
    __syncthreads();
    float tot = 0.f;
#pragma unroll
    for (int i = 0; i < 8; i++) tot += red[i];
    float rinv = rsqrtf(tot * (1.0f / Hc) + EPSc);
#pragma unroll
    for (int i = 0; i < 4; i++) {
        int c = tid + 256 * i;
        float v = xr[c] * w[c] * rinv;
        __nv_bfloat16 h = __float2bfloat16(v);
        g_xnh[(size_t)t * Hc + c] = h;
        g_xnl[(size_t)t * Hc + c] = __float2bfloat16(v - __bfloat162float(h));
    }
}

// ============================================================
// Tiled windowed GQA attention with sink (unchanged from R6)
// ============================================================
__global__ __launch_bounds__(256, 1) void attn_kernel(
    const float* __restrict__ qkvb, const float* __restrict__ kvc,
    const int* __restrict__ pidx, const float* __restrict__ sinks) {
    extern __shared__ float sm[];
    float* Ks = sm;
    float* Vs = Ks + AT_KV;
    float* Qs = Vs + AT_KV;
    float* Ss = Qs + AT_Q;
    float* Rd = Ss + AT_S;

    const int qt = blockIdx.x, kvh = blockIdx.y, b = blockIdx.z;
    const int q0 = qt * 16;
    const int tid = threadIdx.x;

    for (int i = tid; i < 143 * 16; i += 256) {
        int kk = i >> 4, d = (i & 15) * 4;
        int kpos = 769 + q0 + kk;
        const float *kp, *vp;
        if (kpos >= Sq - Qc) {
            int tt = b * Qc + (kpos - (Sq - Qc));
            kp = qkvb + (size_t)tt * QKVW + (NQc + kvh) * HDc + d;
            vp = qkvb + (size_t)tt * QKVW + (NQc + NKVc + kvh) * HDc + d;
        } else {
            int pg = pidx[b * Pc + (kpos >> 7)];
            size_t bb = ((size_t)(pg * 2) * PSc + (kpos & 127)) * (NKVc * HDc) + kvh * HDc + d;
            kp = kvc + bb;
            vp = kvc + bb + (size_t)PSc * NKVc * HDc;
        }
        *(float4*)(Ks + kk * 68 + d) = *(const float4*)kp;
        *(float4*)(Vs + kk * 68 + d) = *(const float4*)vp;
    }
    for (int i = tid; i < 1024; i += 256) {
        int h = i >> 8, qq = (i >> 4) & 15, d = (i & 15) * 4;
        int t = b * Qc + q0 + qq;
        float4 v = *(const float4*)(qkvb + (size_t)t * QKVW + (kvh * 4 + h) * HDc + d);
        v.x *= SCALEc; v.y *= SCALEc; v.z *= SCALEc; v.w *= SCALEc;
        *(float4*)(Qs + (h * 16 + qq) * 64 + d) = v;
    }
    __syncthreads();

    {
        const int qq = tid >> 4, lane = tid & 15;
        float acc[8][4];
#pragma unroll
        for (int j = 0; j < 8; j++)
#pragma unroll
            for (int h = 0; h < 4; h++) acc[j][h] = 0.f;
#pragma unroll
        for (int dc = 0; dc < 4; dc++) {
            float4 qr[4][4];
#pragma unroll
            for (int h = 0; h < 4; h++)
#pragma unroll
                for (int dd = 0; dd < 4; dd++)
                    qr[h][dd] = *(float4*)(Qs + (h * 16 + qq) * 64 + dc * 16 + dd * 4);
#pragma unroll
            for (int j = 0; j < 8; j++) {
                int kk = qq + lane + 16 * j;
                const float* kr = Ks + kk * 68 + dc * 16;
#pragma unroll
                for (int dd = 0; dd < 4; dd++) {
                    float4 k4 = *(const float4*)(kr + dd * 4);
#pragma unroll
                    for (int h = 0; h < 4; h++)
                        acc[j][h] += qr[h][dd].x * k4.x + qr[h][dd].y * k4.y +
                                     qr[h][dd].z * k4.z + qr[h][dd].w * k4.w;
                }
            }
        }
#pragma unroll
        for (int j = 0; j < 8; j++) {
            int l = lane + 16 * j;
#pragma unroll
            for (int h = 0; h < 4; h++) Ss[(qq * 128 + l) * 4 + h] = acc[j][h];
        }
    }
    __syncthreads();

    {
        const int row = tid >> 2, l2 = tid & 3;
        const int sq = row >> 2, sh = row & 3;
        float m = -1e30f;
        for (int k = l2; k < 128; k += 4) m = fmaxf(m, Ss[(sq * 128 + k) * 4 + sh]);
        m = fmaxf(m, __shfl_xor_sync(~0u, m, 1));
        m = fmaxf(m, __shfl_xor_sync(~0u, m, 2));
        float sum = 0.f;
        for (int k = l2; k < 128; k += 4) {
            float p = expf(Ss[(sq * 128 + k) * 4 + sh] - m);
            Ss[(sq * 128 + k) * 4 + sh] = p;
            sum += p;
        }
        sum += __shfl_xor_sync(~0u, sum, 1);
        sum += __shfl_xor_sync(~0u, sum, 2);
        if (l2 == 0) Rd[sq * 4 + sh] = 1.0f / (sum + expf(sinks[kvh * 4 + sh] - m));
    }
    __syncthreads();

    {
        const int qq = tid >> 4, lane = tid & 15;
        const int d = lane * 4;
        float4 oa[4];
#pragma unroll
        for (int h = 0; h < 4; h++) oa[h] = make_float4(0.f, 0.f, 0.f, 0.f);
        for (int l = 0; l < 128; l++) {
            float4 v = *(const float4*)(Vs + (qq + l) * 68 + d);
            const float* pr = Ss + (qq * 128 + l) * 4;
#pragma unroll
            for (int h = 0; h < 4; h++) {
                float p = pr[h];
                oa[h].x += p * v.x; oa[h].y += p * v.y;
                oa[h].z += p * v.z; oa[h].w += p * v.w;
            }
        }
        int t = b * Qc + q0 + qq;
#pragma unroll
        for (int h = 0; h < 4; h++) {
            float r = Rd[qq * 4 + h];
            float x0 = oa[h].x * r, x1 = oa[h].y * r, x2 = oa[h].z * r, x3 = oa[h].w * r;
            size_t p2 = (size_t)t * Hc + (kvh * 4 + h) * HDc + d;
            uint2 hh, ll;
            __nv_bfloat16 b0 = __float2bfloat16(x0), b1 = __float2bfloat16(x1);
            __nv_bfloat16 b2 = __float2bfloat16(x2), b3 = __float2bfloat16(x3);
            hh.x = ((uint32_t)__bfloat16_as_ushort(b1) << 16) | __bfloat16_as_ushort(b0);
            hh.y = ((uint32_t)__bfloat16_as_ushort(b3) << 16) | __bfloat16_as_ushort(b2);
            __nv_bfloat16 c0 = __float2bfloat16(x0 - __bfloat162float(b0));
            __nv_bfloat16 c1 = __float2bfloat16(x1 - __bfloat162float(b1));
            __nv_bfloat16 c2 = __float2bfloat16(x2 - __bfloat162float(b2));
            __nv_bfloat16 c3 = __float2bfloat16(x3 - __bfloat162float(b3));
            ll.x = ((uint32_t)__bfloat16_as_ushort(c1) << 16) | __bfloat16_as_ushort(c0);
            ll.y = ((uint32_t)__bfloat16_as_ushort(c3) << 16) | __bfloat16_as_ushort(c2);
            *(uint2*)(g_ath + p2) = hh;
            *(uint2*)(g_atl + p2) = ll;
        }
    }
}

// ============================================================
// Router: rmsnorm(ln2) -> x2 (bf16 split), logits, top-2 weights
// ============================================================
__global__ void router_kernel(const float* __restrict__ ln2,
                              const float* __restrict__ Wr,
                              const float* __restrict__ br) {
    int t = blockIdx.x, tid = threadIdx.x;
    __shared__ float sx[Hc];
    __shared__ float red[8];
    __shared__ float lg[Ec];
    const float* hr = g_h + (size_t)t * Hc;
    float ss = 0.f;
#pragma unroll
    for (int i = 0; i < 4; i++) { float v = hr[tid + 256 * i]; ss += v * v; }
#pragma unroll
    for (int o = 16; o; o >>= 1) ss += __shfl_xor_sync(~0u, ss, o);
    if ((tid & 31) == 0) red[tid >> 5] = ss;
    __syncthreads();
    float tot = 0.f;
#pragma unroll
    for (int i = 0; i < 8; i++) tot += red[i];
    float rinv = rsqrtf(tot * (1.0f / Hc) + EPSc);
#pragma unroll
    for (int i = 0; i < 4; i++) {
        int c = tid + 256 * i;
        float v = hr[c] * ln2[c] * rinv;
        sx[c] = v;
        __nv_bfloat16 hb = __float2bfloat16(v);
        g_x2h[(size_t)t * Hc + c] = hb;
        g_x2l[(size_t)t * Hc + c] = __float2bfloat16(v - __bfloat162float(hb));
    }
    __syncthreads();
    int w = tid >> 5, lane = tid & 31;
    float s = 0.f;
    for (int c = lane; c < Hc; c += 32) s += sx[c] * Wr[c * Ec + w];
#pragma unroll
    for (int o = 16; o; o >>= 1) s += __shfl_xor_sync(~0u, s, o);
    if (lane == 0) lg[w] = s + br[w];
    __syncthreads();
    if (tid == 0) {
        int i0 = 0; float v0 = lg[0];
#pragma unroll
        for (int e = 1; e < Ec; e++) if (lg[e] > v0) { v0 = lg[e]; i0 = e; }
        int i1 = -1; float v1 = -1e30f;
#pragma unroll
        for (int e = 0; e < Ec; e++) {
            if (e == i0) continue;
            if (lg[e] > v1) { v1 = lg[e]; i1 = e; }
        }
        float e1 = expf(v1 - v0);
        g_eidx[t * 2] = i0; g_eidx[t * 2 + 1] = i1;
        g_ewt[t * 2] = 1.0f / (1.0f + e1);
        g_ewt[t * 2 + 1] = e1 / (1.0f + e1);
    }
}

// ============================================================
// Bucket tokens by expert with 64-aligned padded regions + tile map
// ============================================================
__global__ void bucket_kernel() {
    __shared__ int c1[Ec], c2[Ec], po[Ec];
    int tid = threadIdx.x;
    if (tid < Ec) { c1[tid] = 0; c2[tid] = 0; }
    for (int i = tid; i < SLOTS; i += 256) g_tok[i] = -1;
    __syncthreads();
    for (int i = tid; i < Tc * 2; i += 256) atomicAdd(&c1[g_eidx[i]], 1);
    __syncthreads();
    if (tid == 0) {
        int run = 0, nt = 0;
        for (int e = 0; e < Ec; e++) {
            po[e] = run;
            g_poff[e] = run;
            int te = (c1[e] + 63) >> 6;
            for (int j = 0; j < te; j++) g_tile_e[nt++] = e;
            run += te * 64;
        }
        g_ntiles = nt;
    }
    __syncthreads();
    if (tid < Ec) g_cnt[tid] = c1[tid];
    for (int i = tid; i < Tc * 2; i += 256) {
        int e = g_eidx[i];
        int r = atomicAdd(&c2[e], 1);
        int slot = po[e] + r;
        g_tok[slot] = i >> 1;
        g_slotof[i] = slot;
    }
}

// ============================================================
// Final combine
// ============================================================
__global__ void combine_kernel(float* __restrict__ out) {
    int t = blockIdx.x, tid = threadIdx.x;
    float w0 = g_ewt[t * 2], w1 = g_ewt[t * 2 + 1];
    int s0 = g_slotof[t * 2], s1 = g_slotof[t * 2 + 1];
#pragma unroll
    for (int i = 0; i < 4; i++) {
        int c = tid + 256 * i;
        out[(size_t)t * Hc + c] = g_h[(size_t)t * Hc + c]
                                + w0 * g_eo[(size_t)s0 * Hc + c]
                                + w1 * g_eo[(size_t)s1 * Hc + c];
    }
}

// ============================================================
extern "C" void kernel_launch(void* const* d_in, const int* in_sizes, int n_in,
                              void* d_out, int out_size) {
    const float* hidden = (const float*)d_in[0];
    const float* kvc    = (const float*)d_in[1];
    const int*   pidx   = (const int*)d_in[3];
    const float* sinks  = (const float*)d_in[4];
    const float* w_qkv  = (const float*)d_in[5];
    const float* b_qkv  = (const float*)d_in[6];
    const float* w_o    = (const float*)d_in[7];
    const float* b_o    = (const float*)d_in[8];
    const float* ln1    = (const float*)d_in[9];
    const float* ln2    = (const float*)d_in[10];
    const float* w_r    = (const float*)d_in[11];
    const float* b_r    = (const float*)d_in[12];
    const float* w_gu   = (const float*)d_in[13];
    const float* b_gu   = (const float*)d_in[14];
    const float* w_d    = (const float*)d_in[15];
    const float* b_d    = (const float*)d_in[16];
    float* out = (float*)d_out;

    void *pq, *ph;
    void *pxh, *pxl, *pah, *pal, *px2h, *px2l, *pacth, *pactl;
    void *pwqh, *pwql, *pwoh, *pwol, *pwguh, *pwgul, *pwdh, *pwdl;
    cudaGetSymbolAddress(&pq, g_qkv);
    cudaGetSymbolAddress(&ph, g_h);
    cudaGetSymbolAddress(&pxh, g_xnh);  cudaGetSymbolAddress(&pxl, g_xnl);
    cudaGetSymbolAddress(&pah, g_ath);  cudaGetSymbolAddress(&pal, g_atl);
    cudaGetSymbolAddress(&px2h, g_x2h); cudaGetSymbolAddress(&px2l, g_x2l);
    cudaGetSymbolAddress(&pacth, g_act_hi); cudaGetSymbolAddress(&pactl, g_act_lo);
    cudaGetSymbolAddress(&pwqh, g_wqh); cudaGetSymbolAddress(&pwql, g_wql);
    cudaGetSymbolAddress(&pwoh, g_woh); cudaGetSymbolAddress(&pwol, g_wol);
    cudaGetSymbolAddress(&pwguh, g_wguh); cudaGetSymbolAddress(&pwgul, g_wgul);
    cudaGetSymbolAddress(&pwdh, g_wdh);   cudaGetSymbolAddress(&pwdl, g_wdl);

    cudaFuncSetAttribute(mma_gemm<0, QKVW>, cudaFuncAttributeMaxDynamicSharedMemorySize, GEMM_SMEM);
    cudaFuncSetAttribute(mma_gemm<1, Hc>, cudaFuncAttributeMaxDynamicSharedMemorySize, GEMM_SMEM);
    cudaFuncSetAttribute(mma_gemm<2, 2 * FFNc>, cudaFuncAttributeMaxDynamicSharedMemorySize, GEMM_SMEM);
    cudaFuncSetAttribute(mma_gemm<3, Hc>, cudaFuncAttributeMaxDynamicSharedMemorySize, GEMM_SMEM);
    cudaFuncSetAttribute(attn_kernel, cudaFuncAttributeMaxDynamicSharedMemorySize, ATT_SMEM);

    // ---- side stream for weight converts (fork/join, capture-safe) ----
    cudaStream_t s1;
    cudaStreamCreate(&s1);
    cudaEvent_t e0, e1, e2;
    cudaEventCreateWithFlags(&e0, cudaEventDisableTiming);
    cudaEventCreateWithFlags(&e1, cudaEventDisableTiming);
    cudaEventCreateWithFlags(&e2, cudaEventDisableTiming);

    cudaEventRecord(e0, 0);
    cudaStreamWaitEvent(s1, e0, 0);
    {
        int n4;
        n4 = Hc * QKVW / 4;
        convert_split_kernel<<<(n4 + 255) / 256, 256, 0, s1>>>(
            (const float4*)w_qkv, (uint2*)pwqh, (uint2*)pwql, n4);
        n4 = Hc * Hc / 4;
        convert_split_kernel<<<(n4 + 255) / 256, 256, 0, s1>>>(
            (const float4*)w_o, (uint2*)pwoh, (uint2*)pwol, n4);
        cudaEventRecord(e1, s1);
        n4 = Ec * Hc * 2 * FFNc / 4;
        convert_split_kernel<<<(n4 + 255) / 256, 256, 0, s1>>>(
            (const float4*)w_gu, (uint2*)pwguh, (uint2*)pwgul, n4);
        n4 = Ec * FFNc * Hc / 4;
        convert_split_kernel<<<(n4 + 255) / 256, 256, 0, s1>>>(
            (const float4*)w_d, (uint2*)pwdh, (uint2*)pwdl, n4);
        cudaEventRecord(e2, s1);
    }

    // main stream
    rmsnorm1_kernel<<<Tc, 256>>>(hidden, ln1);
    cudaStreamWaitEvent(0, e1, 0);   // need wqkv + wo
    mma_gemm<0, QKVW><<<dim3(QKVW / 64, Tc / 64, 1), 256, GEMM_SMEM>>>(
        (const __nv_bfloat16*)pxh, (const __nv_bfloat16*)pxl,
        (const __nv_bfloat16*)pwqh, (const __nv_bfloat16*)pwql,
        b_qkv, nullptr, (float*)pq);
    attn_kernel<<<dim3(8, NKVc, Bc), 256, ATT_SMEM>>>(
        (const float*)pq, kvc, pidx, sinks);
    mma_gemm<1, Hc><<<dim3(Hc / 64, Tc / 64, 1), 256, GEMM_SMEM>>>(
        (const __nv_bfloat16*)pah, (const __nv_bfloat16*)pal,
        (const __nv_bfloat16*)pwoh, (const __nv_bfloat16*)pwol,
        b_o, hidden, (float*)ph);
    router_kernel<<<Tc, 256>>>(ln2, w_r, b_r);
    bucket_kernel<<<1, 256>>>();
    cudaStreamWaitEvent(0, e2, 0);   // need wgu + wd
    mma_gemm<2, 2 * FFNc><<<dim3(2 * FFNc / 64, MAXTILES, 1), 256, GEMM_SMEM>>>(
        (const __nv_bfloat16*)px2h, (const __nv_bfloat16*)px2l,
        (const __nv_bfloat16*)pwguh, (const __nv_bfloat16*)pwgul,
        b_gu, nullptr, nullptr);
    mma_gemm<3, Hc><<<dim3(Hc / 64, MAXTILES, 1), 256, GEMM_SMEM>>>(
        (const __nv_bfloat16*)pacth, (const __nv_bfloat16*)pactl,
        (const __nv_bfloat16*)pwdh, (const __nv_bfloat16*)pwdl,
        b_d, nullptr, nullptr);
    combine_kernel<<<Tc, 256>>>(out);
}